// round 1
// baseline (speedup 1.0000x reference)
#include <cuda_runtime.h>
#include <math.h>

#define D_MODEL 1024
#define FFN_DIM 4096
#define N_HEADS 16
#define HEAD_DIM 64
#define SEQLEN 2048
#define BATCH 2
#define NTOK (BATCH * SEQLEN)

// ---------------- scratch (device globals: no runtime allocation) ----------
__device__ float g_q[NTOK * D_MODEL];
__device__ float g_k[NTOK * D_MODEL];
__device__ float g_v[NTOK * D_MODEL];
__device__ float g_ctx[NTOK * D_MODEL];
__device__ float g_x1[NTOK * D_MODEL];
__device__ float g_x2[NTOK * D_MODEL];
__device__ float g_ffn[(size_t)NTOK * FFN_DIM];

// ---------------- GEMM: C[M,N] = A[M,K] @ W[K,N] + bias (opt ReLU) ---------
// 128x128 block, BK=8, 256 threads, 8x8 per thread, fragments split as
// tx*4 / 64+tx*4 so LDS.128 reads are conflict-free.
template <int RELU>
__global__ __launch_bounds__(256) void gemm_bias_kernel(
    const float* __restrict__ A, const float* __restrict__ W,
    const float* __restrict__ bias, float* __restrict__ C,
    int M, int N, int K)
{
    __shared__ float As[8][128];
    __shared__ float Bs[8][128];
    const int tid = threadIdx.x;
    const int tx = tid & 15, ty = tid >> 4;
    const int rowBase = blockIdx.y * 128;
    const int colBase = blockIdx.x * 128;

    const int aRow = tid >> 1, aCol = (tid & 1) << 2;
    const int bRow = tid >> 5, bCol = (tid & 31) << 2;

    float acc[8][8];
#pragma unroll
    for (int i = 0; i < 8; i++)
#pragma unroll
        for (int j = 0; j < 8; j++) acc[i][j] = 0.f;

    const float* Ag = A + (size_t)(rowBase + aRow) * K + aCol;
    const float* Wg = W + (size_t)bRow * N + colBase + bCol;

    for (int k0 = 0; k0 < K; k0 += 8) {
        float4 av = *(const float4*)(Ag + k0);
        float4 bv = *(const float4*)(Wg + (size_t)k0 * N);
        As[aCol + 0][aRow] = av.x;
        As[aCol + 1][aRow] = av.y;
        As[aCol + 2][aRow] = av.z;
        As[aCol + 3][aRow] = av.w;
        *(float4*)&Bs[bRow][bCol] = bv;
        __syncthreads();
#pragma unroll
        for (int kk = 0; kk < 8; kk++) {
            float a[8], bf[8];
            *(float4*)&a[0]  = *(const float4*)&As[kk][ty * 4];
            *(float4*)&a[4]  = *(const float4*)&As[kk][64 + ty * 4];
            *(float4*)&bf[0] = *(const float4*)&Bs[kk][tx * 4];
            *(float4*)&bf[4] = *(const float4*)&Bs[kk][64 + tx * 4];
#pragma unroll
            for (int i = 0; i < 8; i++)
#pragma unroll
                for (int j = 0; j < 8; j++)
                    acc[i][j] = fmaf(a[i], bf[j], acc[i][j]);
        }
        __syncthreads();
    }

#pragma unroll
    for (int ih = 0; ih < 2; ih++)
#pragma unroll
        for (int i = 0; i < 4; i++) {
            int r = rowBase + ih * 64 + ty * 4 + i;
#pragma unroll
            for (int jh = 0; jh < 2; jh++) {
                int c = colBase + jh * 64 + tx * 4;
                float4 bb = *(const float4*)(bias + c);
                float4 o;
                o.x = acc[ih * 4 + i][jh * 4 + 0] + bb.x;
                o.y = acc[ih * 4 + i][jh * 4 + 1] + bb.y;
                o.z = acc[ih * 4 + i][jh * 4 + 2] + bb.z;
                o.w = acc[ih * 4 + i][jh * 4 + 3] + bb.w;
                if (RELU) {
                    o.x = fmaxf(o.x, 0.f); o.y = fmaxf(o.y, 0.f);
                    o.z = fmaxf(o.z, 0.f); o.w = fmaxf(o.w, 0.f);
                }
                *(float4*)(C + (size_t)r * N + c) = o;
            }
        }
}

// ---------------- Flash attention: 64-query blocks, online softmax ---------
// Q/K/V layouts: [tok, D] with head h occupying cols h*64..h*64+63.
// smem: Qs[64][68] (row,d), KP[64][68] (KT: [d][k], reused as P: [row][k]),
//       Vs[64][68] ([k][d]).
#define ATT_PAD 68
#define ATT_SMEM (3 * 64 * ATT_PAD * 4)

__global__ __launch_bounds__(256) void attention_kernel(
    const float* __restrict__ Q, const float* __restrict__ K,
    const float* __restrict__ V, float* __restrict__ O)
{
    extern __shared__ float sm[];
    float* Qs = sm;
    float* KP = sm + 64 * ATT_PAD;
    float* Vs = sm + 2 * 64 * ATT_PAD;

    const int tid = threadIdx.x;
    const int tx = tid & 15;
    const int ty = tid >> 4;
    const int qb = blockIdx.x, h = blockIdx.y, b = blockIdx.z;

    const size_t qbase = ((size_t)(b * SEQLEN) + qb * 64) * D_MODEL + h * HEAD_DIM;
    const size_t kvstart = (size_t)(b * SEQLEN) * D_MODEL + h * HEAD_DIM;

    // load Q tile (scaled by 1/sqrt(64))
#pragma unroll
    for (int i = 0; i < 4; i++) {
        int e = tid + i * 256;
        int r = e >> 4, c = (e & 15) << 2;
        float4 qv = *(const float4*)(Q + qbase + (size_t)r * D_MODEL + c);
        float4 qs = {qv.x * 0.125f, qv.y * 0.125f, qv.z * 0.125f, qv.w * 0.125f};
        *(float4*)&Qs[r * ATT_PAD + c] = qs;
    }

    float m[4], l[4], acc[4][4];
#pragma unroll
    for (int i = 0; i < 4; i++) {
        m[i] = -1e30f; l[i] = 0.f;
#pragma unroll
        for (int j = 0; j < 4; j++) acc[i][j] = 0.f;
    }

    for (int kb = 0; kb < SEQLEN / 64; kb++) {
        __syncthreads();   // previous PV reads of KP/Vs done
        const size_t kvbase = kvstart + (size_t)(kb * 64) * D_MODEL;
#pragma unroll
        for (int i = 0; i < 4; i++) {
            int e = tid + i * 256;
            int r = e >> 4, c = (e & 15) << 2;
            float4 kv = *(const float4*)(K + kvbase + (size_t)r * D_MODEL + c);
            KP[(c + 0) * ATT_PAD + r] = kv.x;   // transposed: KT[d][k]
            KP[(c + 1) * ATT_PAD + r] = kv.y;
            KP[(c + 2) * ATT_PAD + r] = kv.z;
            KP[(c + 3) * ATT_PAD + r] = kv.w;
            float4 vv = *(const float4*)(V + kvbase + (size_t)r * D_MODEL + c);
            *(float4*)&Vs[r * ATT_PAD + c] = vv;
        }
        __syncthreads();

        // S = Qs @ KT : rows ty+16i, cols tx*4+j
        float s[4][4];
#pragma unroll
        for (int i = 0; i < 4; i++)
#pragma unroll
            for (int j = 0; j < 4; j++) s[i][j] = 0.f;

#pragma unroll 16
        for (int dd = 0; dd < 64; dd++) {
            float4 kj = *(const float4*)&KP[dd * ATT_PAD + tx * 4];
            float qv[4];
#pragma unroll
            for (int i = 0; i < 4; i++) qv[i] = Qs[(ty + 16 * i) * ATT_PAD + dd];
#pragma unroll
            for (int i = 0; i < 4; i++) {
                s[i][0] = fmaf(qv[i], kj.x, s[i][0]);
                s[i][1] = fmaf(qv[i], kj.y, s[i][1]);
                s[i][2] = fmaf(qv[i], kj.z, s[i][2]);
                s[i][3] = fmaf(qv[i], kj.w, s[i][3]);
            }
        }

        // online softmax (row stats reduced over the 16-lane tx group)
#pragma unroll
        for (int i = 0; i < 4; i++) {
            float tm = fmaxf(fmaxf(s[i][0], s[i][1]), fmaxf(s[i][2], s[i][3]));
#pragma unroll
            for (int o = 8; o; o >>= 1)
                tm = fmaxf(tm, __shfl_xor_sync(0xffffffffu, tm, o));
            float mn = fmaxf(m[i], tm);
            float alpha = __expf(m[i] - mn);
            float rs = 0.f;
#pragma unroll
            for (int j = 0; j < 4; j++) { s[i][j] = __expf(s[i][j] - mn); rs += s[i][j]; }
#pragma unroll
            for (int o = 8; o; o >>= 1)
                rs += __shfl_xor_sync(0xffffffffu, rs, o);
            l[i] = l[i] * alpha + rs;
            m[i] = mn;
#pragma unroll
            for (int j = 0; j < 4; j++) acc[i][j] *= alpha;
        }

        __syncthreads();   // all KT reads done, safe to overwrite with P
#pragma unroll
        for (int i = 0; i < 4; i++) {
            float4 p = {s[i][0], s[i][1], s[i][2], s[i][3]};
            *(float4*)&KP[(ty + 16 * i) * ATT_PAD + tx * 4] = p;
        }
        __syncthreads();

        // O += P @ V : rows ty+16i, dims tx*4+j
#pragma unroll 16
        for (int kk = 0; kk < 64; kk++) {
            float4 vj = *(const float4*)&Vs[kk * ATT_PAD + tx * 4];
            float pv[4];
#pragma unroll
            for (int i = 0; i < 4; i++) pv[i] = KP[(ty + 16 * i) * ATT_PAD + kk];
#pragma unroll
            for (int i = 0; i < 4; i++) {
                acc[i][0] = fmaf(pv[i], vj.x, acc[i][0]);
                acc[i][1] = fmaf(pv[i], vj.y, acc[i][1]);
                acc[i][2] = fmaf(pv[i], vj.z, acc[i][2]);
                acc[i][3] = fmaf(pv[i], vj.w, acc[i][3]);
            }
        }
    }

#pragma unroll
    for (int i = 0; i < 4; i++) {
        int r = ty + 16 * i;
        float inv = 1.f / l[i];
        float4 o = {acc[i][0] * inv, acc[i][1] * inv, acc[i][2] * inv, acc[i][3] * inv};
        *(float4*)(O + qbase + (size_t)r * D_MODEL + tx * 4) = o;
    }
}

// ---------------- add + LayerNorm ------------------------------------------
__global__ __launch_bounds__(256) void add_ln_kernel(
    const float* __restrict__ A, const float* __restrict__ Hh,
    const float* __restrict__ G, const float* __restrict__ Bt,
    float* __restrict__ Out)
{
    const int row = blockIdx.x;
    const int t = threadIdx.x;
    const size_t base = (size_t)row * D_MODEL + t * 4;
    float4 x = *(const float4*)(A + base);
    float4 y = *(const float4*)(Hh + base);
    float4 v = {x.x + y.x, x.y + y.y, x.z + y.z, x.w + y.w};
    float s  = v.x + v.y + v.z + v.w;
    float s2 = v.x * v.x + v.y * v.y + v.z * v.z + v.w * v.w;
#pragma unroll
    for (int o = 16; o; o >>= 1) {
        s  += __shfl_xor_sync(0xffffffffu, s, o);
        s2 += __shfl_xor_sync(0xffffffffu, s2, o);
    }
    __shared__ float sh[16];
    __shared__ float stats[2];
    const int w = t >> 5;
    if ((t & 31) == 0) { sh[w] = s; sh[8 + w] = s2; }
    __syncthreads();
    if (t == 0) {
        float S = 0.f, S2 = 0.f;
        for (int i = 0; i < 8; i++) { S += sh[i]; S2 += sh[8 + i]; }
        float mu = S * (1.f / D_MODEL);
        float var = S2 * (1.f / D_MODEL) - mu * mu;
        stats[0] = mu;
        stats[1] = rsqrtf(var + 1e-5f);
    }
    __syncthreads();
    const float mu = stats[0], r = stats[1];
    float4 g4 = *(const float4*)(G + t * 4);
    float4 b4 = *(const float4*)(Bt + t * 4);
    float4 o;
    o.x = (v.x - mu) * r * g4.x + b4.x;
    o.y = (v.y - mu) * r * g4.y + b4.y;
    o.z = (v.z - mu) * r * g4.z + b4.z;
    o.w = (v.w - mu) * r * g4.w + b4.w;
    *(float4*)(Out + base) = o;
}

// ---------------- launch ---------------------------------------------------
static void run_gemm(const float* A, const float* W, const float* bias,
                     float* C, int M, int N, int K, bool relu)
{
    dim3 grid(N / 128, M / 128);
    if (relu) gemm_bias_kernel<1><<<grid, 256>>>(A, W, bias, C, M, N, K);
    else      gemm_bias_kernel<0><<<grid, 256>>>(A, W, bias, C, M, N, K);
}

extern "C" void kernel_launch(void* const* d_in, const int* in_sizes, int n_in,
                              void* d_out, int out_size)
{
    const float* hid   = (const float*)d_in[0];
    const float* enc   = (const float*)d_in[1];
    const float* sa_wq = (const float*)d_in[2];
    const float* sa_bq = (const float*)d_in[3];
    const float* sa_wk = (const float*)d_in[4];
    const float* sa_bk = (const float*)d_in[5];
    const float* sa_wv = (const float*)d_in[6];
    const float* sa_bv = (const float*)d_in[7];
    const float* ln1_g = (const float*)d_in[8];
    const float* ln1_b = (const float*)d_in[9];
    const float* ca_wq = (const float*)d_in[10];
    const float* ca_bq = (const float*)d_in[11];
    const float* ca_wk = (const float*)d_in[12];
    const float* ca_bk = (const float*)d_in[13];
    const float* ca_wv = (const float*)d_in[14];
    const float* ca_bv = (const float*)d_in[15];
    const float* ln2_g = (const float*)d_in[16];
    const float* ln2_b = (const float*)d_in[17];
    const float* fc1_w = (const float*)d_in[18];
    const float* fc1_b = (const float*)d_in[19];
    const float* fc2_w = (const float*)d_in[20];
    const float* fc2_b = (const float*)d_in[21];
    const float* ln3_g = (const float*)d_in[22];
    const float* ln3_b = (const float*)d_in[23];

    float *q, *k, *v, *ctx, *x1, *x2, *ffn;
    cudaGetSymbolAddress((void**)&q,   g_q);
    cudaGetSymbolAddress((void**)&k,   g_k);
    cudaGetSymbolAddress((void**)&v,   g_v);
    cudaGetSymbolAddress((void**)&ctx, g_ctx);
    cudaGetSymbolAddress((void**)&x1,  g_x1);
    cudaGetSymbolAddress((void**)&x2,  g_x2);
    cudaGetSymbolAddress((void**)&ffn, g_ffn);

    cudaFuncSetAttribute(attention_kernel,
                         cudaFuncAttributeMaxDynamicSharedMemorySize, ATT_SMEM);

    const dim3 att_grid(SEQLEN / 64, N_HEADS, BATCH);

    // ---- self-attention ----
    run_gemm(hid, sa_wq, sa_bq, q, NTOK, D_MODEL, D_MODEL, false);
    run_gemm(hid, sa_wk, sa_bk, k, NTOK, D_MODEL, D_MODEL, false);
    run_gemm(hid, sa_wv, sa_bv, v, NTOK, D_MODEL, D_MODEL, false);
    attention_kernel<<<att_grid, 256, ATT_SMEM>>>(q, k, v, ctx);
    add_ln_kernel<<<NTOK, 256>>>(hid, ctx, ln1_g, ln1_b, x1);

    // ---- cross-attention ----
    run_gemm(x1,  ca_wq, ca_bq, q, NTOK, D_MODEL, D_MODEL, false);
    run_gemm(enc, ca_wk, ca_bk, k, NTOK, D_MODEL, D_MODEL, false);
    run_gemm(enc, ca_wv, ca_bv, v, NTOK, D_MODEL, D_MODEL, false);
    attention_kernel<<<att_grid, 256, ATT_SMEM>>>(q, k, v, ctx);
    add_ln_kernel<<<NTOK, 256>>>(x1, ctx, ln2_g, ln2_b, x2);

    // ---- feed-forward ----
    run_gemm(x2,  fc1_w, fc1_b, ffn, NTOK, FFN_DIM, D_MODEL, true);
    run_gemm(ffn, fc2_w, fc2_b, ctx, NTOK, D_MODEL, FFN_DIM, false);
    add_ln_kernel<<<NTOK, 256>>>(x2, ctx, ln3_g, ln3_b, (float*)d_out);
}

// round 4
// speedup vs baseline: 1.5499x; 1.5499x over previous
#include <cuda_runtime.h>
#include <stdint.h>

#define D_MODEL 1024
#define FFN_DIM 4096
#define N_HEADS 16
#define HEAD_DIM 64
#define SEQLEN 2048
#define BATCH 2
#define NTOK (BATCH * SEQLEN)

// ---------------- scratch (device globals: no runtime allocation) ----------
__device__ float g_q[NTOK * D_MODEL];
__device__ float g_k[NTOK * D_MODEL];
__device__ float g_v[NTOK * D_MODEL];
__device__ float g_ctx[NTOK * D_MODEL];
__device__ float g_x1[NTOK * D_MODEL];
__device__ float g_x2[NTOK * D_MODEL];
__device__ float g_ffn[(size_t)NTOK * FFN_DIM];

// ---------------- tf32 helpers ---------------------------------------------
__device__ __forceinline__ uint32_t f2tf32(float x) {
    uint32_t r;
    asm("cvt.rna.tf32.f32 %0, %1;" : "=r"(r) : "f"(x));
    return r;
}

__device__ __forceinline__ void mma_tf32(
    float* c, const uint32_t* a, const uint32_t* b)
{
    asm volatile(
        "mma.sync.aligned.m16n8k8.row.col.f32.tf32.tf32.f32 "
        "{%0,%1,%2,%3}, {%4,%5,%6,%7}, {%8,%9}, {%0,%1,%2,%3};\n"
        : "+f"(c[0]), "+f"(c[1]), "+f"(c[2]), "+f"(c[3])
        : "r"(a[0]), "r"(a[1]), "r"(a[2]), "r"(a[3]),
          "r"(b[0]), "r"(b[1]));
}

// ---------------- GEMM: C[M,N] = A[M,K] @ W[K,N] + bias (opt ReLU) ---------
// tf32 tensor cores (mma.m16n8k8). 128x128 block tile, BK=16, 256 threads
// (8 warps as 2m x 4n, warp tile 64x32 = 4x4 mma tiles). Double-buffered
// smem; As stored transposed [k][m] (stride 136 => conflict-free frag LDS).
#define GBM 128
#define GBN 128
#define GBK 16
#define GST 136   // smem row stride (mod 32 == 8 -> conflict-free frags)

template <int RELU>
__global__ __launch_bounds__(256, 2) void gemm_tf32_kernel(
    const float* __restrict__ A, const float* __restrict__ W,
    const float* __restrict__ bias, float* __restrict__ C,
    int M, int N, int K)
{
    __shared__ uint32_t As[2][GBK][GST];
    __shared__ uint32_t Bs[2][GBK][GST];

    const int tid  = threadIdx.x;
    const int lane = tid & 31;
    const int warp = tid >> 5;
    const int wm = warp >> 2;      // 0..1
    const int wn = warp & 3;       // 0..3
    const int rowBase = blockIdx.y * GBM;
    const int colBase = blockIdx.x * GBN;

    // A tile loader: 128 rows x 16 k; thread -> row tid>>1, kbase (tid&1)*8
    const int aM = tid >> 1;
    const int aK = (tid & 1) * 8;
    // W tile loader: 16 k x 128 n; thread -> k tid>>4, nbase (tid&15)*4 (+64)
    const int bK = tid >> 4;
    const int bN = (tid & 15) * 4;

    const float* Aptr = A + (size_t)(rowBase + aM) * K + aK;
    const float* Wptr = W + (size_t)bK * N + colBase + bN;

    float acc[4][4][4];
#pragma unroll
    for (int i = 0; i < 4; i++)
#pragma unroll
        for (int j = 0; j < 4; j++)
#pragma unroll
            for (int r = 0; r < 4; r++) acc[i][j][r] = 0.f;

    float4 aReg0, aReg1, bReg0, bReg1;

    // ---- prologue: stage k0 = 0 into buffer 0 ----
    aReg0 = *(const float4*)(Aptr);
    aReg1 = *(const float4*)(Aptr + 4);
    bReg0 = *(const float4*)(Wptr);
    bReg1 = *(const float4*)(Wptr + 64);
    {
        As[0][aK + 0][aM] = f2tf32(aReg0.x);
        As[0][aK + 1][aM] = f2tf32(aReg0.y);
        As[0][aK + 2][aM] = f2tf32(aReg0.z);
        As[0][aK + 3][aM] = f2tf32(aReg0.w);
        As[0][aK + 4][aM] = f2tf32(aReg1.x);
        As[0][aK + 5][aM] = f2tf32(aReg1.y);
        As[0][aK + 6][aM] = f2tf32(aReg1.z);
        As[0][aK + 7][aM] = f2tf32(aReg1.w);
        uint4 p0 = {f2tf32(bReg0.x), f2tf32(bReg0.y), f2tf32(bReg0.z), f2tf32(bReg0.w)};
        uint4 p1 = {f2tf32(bReg1.x), f2tf32(bReg1.y), f2tf32(bReg1.z), f2tf32(bReg1.w)};
        *(uint4*)&Bs[0][bK][bN]      = p0;
        *(uint4*)&Bs[0][bK][bN + 64] = p1;
    }
    __syncthreads();

    int buf = 0;
    for (int k0 = 0; k0 < K; k0 += GBK) {
        const int knext = k0 + GBK;
        if (knext < K) {
            aReg0 = *(const float4*)(Aptr + knext);
            aReg1 = *(const float4*)(Aptr + knext + 4);
            bReg0 = *(const float4*)(Wptr + (size_t)knext * N);
            bReg1 = *(const float4*)(Wptr + (size_t)knext * N + 64);
        }

        // ---- compute on buf ----
#pragma unroll
        for (int ks = 0; ks < 2; ks++) {
            const int kk = ks * 8 + (lane & 3);
            uint32_t af[4][4], bf[4][2];
#pragma unroll
            for (int t = 0; t < 4; t++) {
                const int m = wm * 64 + t * 16 + (lane >> 2);
                af[t][0] = As[buf][kk][m];
                af[t][1] = As[buf][kk][m + 8];
                af[t][2] = As[buf][kk + 4][m];
                af[t][3] = As[buf][kk + 4][m + 8];
            }
#pragma unroll
            for (int t = 0; t < 4; t++) {
                const int n = wn * 32 + t * 8 + (lane >> 2);
                bf[t][0] = Bs[buf][kk][n];
                bf[t][1] = Bs[buf][kk + 4][n];
            }
#pragma unroll
            for (int mt = 0; mt < 4; mt++)
#pragma unroll
                for (int nt = 0; nt < 4; nt++)
                    mma_tf32(acc[mt][nt], af[mt], bf[nt]);
        }

        if (knext < K) {
            const int nb = buf ^ 1;
            As[nb][aK + 0][aM] = f2tf32(aReg0.x);
            As[nb][aK + 1][aM] = f2tf32(aReg0.y);
            As[nb][aK + 2][aM] = f2tf32(aReg0.z);
            As[nb][aK + 3][aM] = f2tf32(aReg0.w);
            As[nb][aK + 4][aM] = f2tf32(aReg1.x);
            As[nb][aK + 5][aM] = f2tf32(aReg1.y);
            As[nb][aK + 6][aM] = f2tf32(aReg1.z);
            As[nb][aK + 7][aM] = f2tf32(aReg1.w);
            uint4 p0 = {f2tf32(bReg0.x), f2tf32(bReg0.y), f2tf32(bReg0.z), f2tf32(bReg0.w)};
            uint4 p1 = {f2tf32(bReg1.x), f2tf32(bReg1.y), f2tf32(bReg1.z), f2tf32(bReg1.w)};
            *(uint4*)&Bs[nb][bK][bN]      = p0;
            *(uint4*)&Bs[nb][bK][bN + 64] = p1;
        }
        __syncthreads();
        buf ^= 1;
    }

    // ---- epilogue: bias (+ReLU), float2 stores ----
#pragma unroll
    for (int mt = 0; mt < 4; mt++) {
        const int r = rowBase + wm * 64 + mt * 16 + (lane >> 2);
#pragma unroll
        for (int nt = 0; nt < 4; nt++) {
            const int cc = colBase + wn * 32 + nt * 8 + (lane & 3) * 2;
            const float2 bb = *(const float2*)(bias + cc);
            float2 o0, o1;
            o0.x = acc[mt][nt][0] + bb.x;
            o0.y = acc[mt][nt][1] + bb.y;
            o1.x = acc[mt][nt][2] + bb.x;
            o1.y = acc[mt][nt][3] + bb.y;
            if (RELU) {
                o0.x = fmaxf(o0.x, 0.f); o0.y = fmaxf(o0.y, 0.f);
                o1.x = fmaxf(o1.x, 0.f); o1.y = fmaxf(o1.y, 0.f);
            }
            *(float2*)(C + (size_t)r * N + cc)       = o0;
            *(float2*)(C + (size_t)(r + 8) * N + cc) = o1;
        }
    }
}

// ---------------- Flash attention: 64-query blocks, online softmax ---------
#define ATT_PAD 68
#define ATT_SMEM (3 * 64 * ATT_PAD * 4)

__global__ __launch_bounds__(256) void attention_kernel(
    const float* __restrict__ Q, const float* __restrict__ K,
    const float* __restrict__ V, float* __restrict__ O)
{
    extern __shared__ float sm[];
    float* Qs = sm;
    float* KP = sm + 64 * ATT_PAD;
    float* Vs = sm + 2 * 64 * ATT_PAD;

    const int tid = threadIdx.x;
    const int tx = tid & 15;
    const int ty = tid >> 4;
    const int qb = blockIdx.x, h = blockIdx.y, b = blockIdx.z;

    const size_t qbase = ((size_t)(b * SEQLEN) + qb * 64) * D_MODEL + h * HEAD_DIM;
    const size_t kvstart = (size_t)(b * SEQLEN) * D_MODEL + h * HEAD_DIM;

#pragma unroll
    for (int i = 0; i < 4; i++) {
        int e = tid + i * 256;
        int r = e >> 4, c = (e & 15) << 2;
        float4 qv = *(const float4*)(Q + qbase + (size_t)r * D_MODEL + c);
        float4 qs = {qv.x * 0.125f, qv.y * 0.125f, qv.z * 0.125f, qv.w * 0.125f};
        *(float4*)&Qs[r * ATT_PAD + c] = qs;
    }

    float m[4], l[4], acc[4][4];
#pragma unroll
    for (int i = 0; i < 4; i++) {
        m[i] = -1e30f; l[i] = 0.f;
#pragma unroll
        for (int j = 0; j < 4; j++) acc[i][j] = 0.f;
    }

    for (int kb = 0; kb < SEQLEN / 64; kb++) {
        __syncthreads();
        const size_t kvbase = kvstart + (size_t)(kb * 64) * D_MODEL;
#pragma unroll
        for (int i = 0; i < 4; i++) {
            int e = tid + i * 256;
            int r = e >> 4, c = (e & 15) << 2;
            float4 kv = *(const float4*)(K + kvbase + (size_t)r * D_MODEL + c);
            KP[(c + 0) * ATT_PAD + r] = kv.x;
            KP[(c + 1) * ATT_PAD + r] = kv.y;
            KP[(c + 2) * ATT_PAD + r] = kv.z;
            KP[(c + 3) * ATT_PAD + r] = kv.w;
            float4 vv = *(const float4*)(V + kvbase + (size_t)r * D_MODEL + c);
            *(float4*)&Vs[r * ATT_PAD + c] = vv;
        }
        __syncthreads();

        float s[4][4];
#pragma unroll
        for (int i = 0; i < 4; i++)
#pragma unroll
            for (int j = 0; j < 4; j++) s[i][j] = 0.f;

#pragma unroll 16
        for (int dd = 0; dd < 64; dd++) {
            float4 kj = *(const float4*)&KP[dd * ATT_PAD + tx * 4];
            float qv[4];
#pragma unroll
            for (int i = 0; i < 4; i++) qv[i] = Qs[(ty + 16 * i) * ATT_PAD + dd];
#pragma unroll
            for (int i = 0; i < 4; i++) {
                s[i][0] = fmaf(qv[i], kj.x, s[i][0]);
                s[i][1] = fmaf(qv[i], kj.y, s[i][1]);
                s[i][2] = fmaf(qv[i], kj.z, s[i][2]);
                s[i][3] = fmaf(qv[i], kj.w, s[i][3]);
            }
        }

#pragma unroll
        for (int i = 0; i < 4; i++) {
            float tm = fmaxf(fmaxf(s[i][0], s[i][1]), fmaxf(s[i][2], s[i][3]));
#pragma unroll
            for (int o = 8; o; o >>= 1)
                tm = fmaxf(tm, __shfl_xor_sync(0xffffffffu, tm, o));
            float mn = fmaxf(m[i], tm);
            float alpha = __expf(m[i] - mn);
            float rs = 0.f;
#pragma unroll
            for (int j = 0; j < 4; j++) { s[i][j] = __expf(s[i][j] - mn); rs += s[i][j]; }
#pragma unroll
            for (int o = 8; o; o >>= 1)
                rs += __shfl_xor_sync(0xffffffffu, rs, o);
            l[i] = l[i] * alpha + rs;
            m[i] = mn;
#pragma unroll
            for (int j = 0; j < 4; j++) acc[i][j] *= alpha;
        }

        __syncthreads();
#pragma unroll
        for (int i = 0; i < 4; i++) {
            float4 p = {s[i][0], s[i][1], s[i][2], s[i][3]};
            *(float4*)&KP[(ty + 16 * i) * ATT_PAD + tx * 4] = p;
        }
        __syncthreads();

#pragma unroll 16
        for (int kk = 0; kk < 64; kk++) {
            float4 vj = *(const float4*)&Vs[kk * ATT_PAD + tx * 4];
            float pv[4];
#pragma unroll
            for (int i = 0; i < 4; i++) pv[i] = KP[(ty + 16 * i) * ATT_PAD + kk];
#pragma unroll
            for (int i = 0; i < 4; i++) {
                acc[i][0] = fmaf(pv[i], vj.x, acc[i][0]);
                acc[i][1] = fmaf(pv[i], vj.y, acc[i][1]);
                acc[i][2] = fmaf(pv[i], vj.z, acc[i][2]);
                acc[i][3] = fmaf(pv[i], vj.w, acc[i][3]);
            }
        }
    }

#pragma unroll
    for (int i = 0; i < 4; i++) {
        int r = ty + 16 * i;
        float inv = 1.f / l[i];
        float4 o = {acc[i][0] * inv, acc[i][1] * inv, acc[i][2] * inv, acc[i][3] * inv};
        *(float4*)(O + qbase + (size_t)r * D_MODEL + tx * 4) = o;
    }
}

// ---------------- add + LayerNorm ------------------------------------------
__global__ __launch_bounds__(256) void add_ln_kernel(
    const float* __restrict__ A, const float* __restrict__ Hh,
    const float* __restrict__ G, const float* __restrict__ Bt,
    float* __restrict__ Out)
{
    const int row = blockIdx.x;
    const int t = threadIdx.x;
    const size_t base = (size_t)row * D_MODEL + t * 4;
    float4 x = *(const float4*)(A + base);
    float4 y = *(const float4*)(Hh + base);
    float4 v = {x.x + y.x, x.y + y.y, x.z + y.z, x.w + y.w};
    float s  = v.x + v.y + v.z + v.w;
    float s2 = v.x * v.x + v.y * v.y + v.z * v.z + v.w * v.w;
#pragma unroll
    for (int o = 16; o; o >>= 1) {
        s  += __shfl_xor_sync(0xffffffffu, s, o);
        s2 += __shfl_xor_sync(0xffffffffu, s2, o);
    }
    __shared__ float sh[16];
    __shared__ float stats[2];
    const int w = t >> 5;
    if ((t & 31) == 0) { sh[w] = s; sh[8 + w] = s2; }
    __syncthreads();
    if (t == 0) {
        float S = 0.f, S2 = 0.f;
        for (int i = 0; i < 8; i++) { S += sh[i]; S2 += sh[8 + i]; }
        float mu = S * (1.f / D_MODEL);
        float var = S2 * (1.f / D_MODEL) - mu * mu;
        stats[0] = mu;
        stats[1] = rsqrtf(var + 1e-5f);
    }
    __syncthreads();
    const float mu = stats[0], r = stats[1];
    float4 g4 = *(const float4*)(G + t * 4);
    float4 b4 = *(const float4*)(Bt + t * 4);
    float4 o;
    o.x = (v.x - mu) * r * g4.x + b4.x;
    o.y = (v.y - mu) * r * g4.y + b4.y;
    o.z = (v.z - mu) * r * g4.z + b4.z;
    o.w = (v.w - mu) * r * g4.w + b4.w;
    *(float4*)(Out + base) = o;
}

// ---------------- launch ---------------------------------------------------
static void run_gemm(const float* A, const float* W, const float* bias,
                     float* C, int M, int N, int K, bool relu)
{
    dim3 grid(N / GBN, M / GBM);
    if (relu) gemm_tf32_kernel<1><<<grid, 256>>>(A, W, bias, C, M, N, K);
    else      gemm_tf32_kernel<0><<<grid, 256>>>(A, W, bias, C, M, N, K);
}

extern "C" void kernel_launch(void* const* d_in, const int* in_sizes, int n_in,
                              void* d_out, int out_size)
{
    const float* hid   = (const float*)d_in[0];
    const float* enc   = (const float*)d_in[1];
    const float* sa_wq = (const float*)d_in[2];
    const float* sa_bq = (const float*)d_in[3];
    const float* sa_wk = (const float*)d_in[4];
    const float* sa_bk = (const float*)d_in[5];
    const float* sa_wv = (const float*)d_in[6];
    const float* sa_bv = (const float*)d_in[7];
    const float* ln1_g = (const float*)d_in[8];
    const float* ln1_b = (const float*)d_in[9];
    const float* ca_wq = (const float*)d_in[10];
    const float* ca_bq = (const float*)d_in[11];
    const float* ca_wk = (const float*)d_in[12];
    const float* ca_bk = (const float*)d_in[13];
    const float* ca_wv = (const float*)d_in[14];
    const float* ca_bv = (const float*)d_in[15];
    const float* ln2_g = (const float*)d_in[16];
    const float* ln2_b = (const float*)d_in[17];
    const float* fc1_w = (const float*)d_in[18];
    const float* fc1_b = (const float*)d_in[19];
    const float* fc2_w = (const float*)d_in[20];
    const float* fc2_b = (const float*)d_in[21];
    const float* ln3_g = (const float*)d_in[22];
    const float* ln3_b = (const float*)d_in[23];

    float *q, *k, *v, *ctx, *x1, *x2, *ffn;
    cudaGetSymbolAddress((void**)&q,   g_q);
    cudaGetSymbolAddress((void**)&k,   g_k);
    cudaGetSymbolAddress((void**)&v,   g_v);
    cudaGetSymbolAddress((void**)&ctx, g_ctx);
    cudaGetSymbolAddress((void**)&x1,  g_x1);
    cudaGetSymbolAddress((void**)&x2,  g_x2);
    cudaGetSymbolAddress((void**)&ffn, g_ffn);

    cudaFuncSetAttribute(attention_kernel,
                         cudaFuncAttributeMaxDynamicSharedMemorySize, ATT_SMEM);

    const dim3 att_grid(SEQLEN / 64, N_HEADS, BATCH);

    // ---- self-attention ----
    run_gemm(hid, sa_wq, sa_bq, q, NTOK, D_MODEL, D_MODEL, false);
    run_gemm(hid, sa_wk, sa_bk, k, NTOK, D_MODEL, D_MODEL, false);
    run_gemm(hid, sa_wv, sa_bv, v, NTOK, D_MODEL, D_MODEL, false);
    attention_kernel<<<att_grid, 256, ATT_SMEM>>>(q, k, v, ctx);
    add_ln_kernel<<<NTOK, 256>>>(hid, ctx, ln1_g, ln1_b, x1);

    // ---- cross-attention ----
    run_gemm(x1,  ca_wq, ca_bq, q, NTOK, D_MODEL, D_MODEL, false);
    run_gemm(enc, ca_wk, ca_bk, k, NTOK, D_MODEL, D_MODEL, false);
    run_gemm(enc, ca_wv, ca_bv, v, NTOK, D_MODEL, D_MODEL, false);
    attention_kernel<<<att_grid, 256, ATT_SMEM>>>(q, k, v, ctx);
    add_ln_kernel<<<NTOK, 256>>>(x1, ctx, ln2_g, ln2_b, x2);

    // ---- feed-forward ----
    run_gemm(x2,  fc1_w, fc1_b, ffn, NTOK, FFN_DIM, D_MODEL, true);
    run_gemm(ffn, fc2_w, fc2_b, ctx, NTOK, D_MODEL, FFN_DIM, false);
    add_ln_kernel<<<NTOK, 256>>>(x2, ctx, ln3_g, ln3_b, (float*)d_out);
}

// round 5
// speedup vs baseline: 2.6083x; 1.6829x over previous
#include <cuda_runtime.h>
#include <stdint.h>

#define D_MODEL 1024
#define FFN_DIM 4096
#define N_HEADS 16
#define HEAD_DIM 64
#define SEQLEN 2048
#define BATCH 2
#define NTOK (BATCH * SEQLEN)

// ---------------- scratch (device globals: no runtime allocation) ----------
__device__ float g_q[NTOK * D_MODEL];
__device__ float g_k[NTOK * D_MODEL];
__device__ float g_v[NTOK * D_MODEL];
__device__ float g_ctx[NTOK * D_MODEL];
__device__ float g_x1[NTOK * D_MODEL];
__device__ float g_x2[NTOK * D_MODEL];
__device__ float g_ffn[(size_t)NTOK * FFN_DIM];

// ---------------- tf32 helpers ---------------------------------------------
__device__ __forceinline__ uint32_t f2tf32(float x) {
    uint32_t r;
    asm("cvt.rna.tf32.f32 %0, %1;" : "=r"(r) : "f"(x));
    return r;
}

__device__ __forceinline__ void mma_tf32(
    float* c, const uint32_t* a, const uint32_t* b)
{
    asm volatile(
        "mma.sync.aligned.m16n8k8.row.col.f32.tf32.tf32.f32 "
        "{%0,%1,%2,%3}, {%4,%5,%6,%7}, {%8,%9}, {%0,%1,%2,%3};\n"
        : "+f"(c[0]), "+f"(c[1]), "+f"(c[2]), "+f"(c[3])
        : "r"(a[0]), "r"(a[1]), "r"(a[2]), "r"(a[3]),
          "r"(b[0]), "r"(b[1]));
}

__device__ __forceinline__ void cp_async16(uint32_t dst_smem, const void* src) {
    asm volatile("cp.async.ca.shared.global [%0], [%1], 16;"
                 :: "r"(dst_smem), "l"(src));
}
__device__ __forceinline__ void cp_async_commit() {
    asm volatile("cp.async.commit_group;");
}
__device__ __forceinline__ void cp_async_wait0() {
    asm volatile("cp.async.wait_group 0;" ::: "memory");
}

// ---------------- GEMM: C[M,N] = A[M,K] @ W[K,N] + bias (opt ReLU) ---------
#define GBM 128
#define GBN 128
#define GBK 16
#define GST 136

template <int RELU>
__global__ __launch_bounds__(256, 2) void gemm_tf32_kernel(
    const float* __restrict__ A, const float* __restrict__ W,
    const float* __restrict__ bias, float* __restrict__ C,
    int M, int N, int K)
{
    __shared__ uint32_t As[2][GBK][GST];
    __shared__ uint32_t Bs[2][GBK][GST];

    const int tid  = threadIdx.x;
    const int lane = tid & 31;
    const int warp = tid >> 5;
    const int wm = warp >> 2;
    const int wn = warp & 3;
    const int rowBase = blockIdx.y * GBM;
    const int colBase = blockIdx.x * GBN;

    const int aM = tid >> 1;
    const int aK = (tid & 1) * 8;
    const int bK = tid >> 4;
    const int bN = (tid & 15) * 4;

    const float* Aptr = A + (size_t)(rowBase + aM) * K + aK;
    const float* Wptr = W + (size_t)bK * N + colBase + bN;

    float acc[4][4][4];
#pragma unroll
    for (int i = 0; i < 4; i++)
#pragma unroll
        for (int j = 0; j < 4; j++)
#pragma unroll
            for (int r = 0; r < 4; r++) acc[i][j][r] = 0.f;

    float4 aReg0, aReg1, bReg0, bReg1;

    aReg0 = *(const float4*)(Aptr);
    aReg1 = *(const float4*)(Aptr + 4);
    bReg0 = *(const float4*)(Wptr);
    bReg1 = *(const float4*)(Wptr + 64);
    {
        As[0][aK + 0][aM] = f2tf32(aReg0.x);
        As[0][aK + 1][aM] = f2tf32(aReg0.y);
        As[0][aK + 2][aM] = f2tf32(aReg0.z);
        As[0][aK + 3][aM] = f2tf32(aReg0.w);
        As[0][aK + 4][aM] = f2tf32(aReg1.x);
        As[0][aK + 5][aM] = f2tf32(aReg1.y);
        As[0][aK + 6][aM] = f2tf32(aReg1.z);
        As[0][aK + 7][aM] = f2tf32(aReg1.w);
        uint4 p0 = {f2tf32(bReg0.x), f2tf32(bReg0.y), f2tf32(bReg0.z), f2tf32(bReg0.w)};
        uint4 p1 = {f2tf32(bReg1.x), f2tf32(bReg1.y), f2tf32(bReg1.z), f2tf32(bReg1.w)};
        *(uint4*)&Bs[0][bK][bN]      = p0;
        *(uint4*)&Bs[0][bK][bN + 64] = p1;
    }
    __syncthreads();

    int buf = 0;
    for (int k0 = 0; k0 < K; k0 += GBK) {
        const int knext = k0 + GBK;
        if (knext < K) {
            aReg0 = *(const float4*)(Aptr + knext);
            aReg1 = *(const float4*)(Aptr + knext + 4);
            bReg0 = *(const float4*)(Wptr + (size_t)knext * N);
            bReg1 = *(const float4*)(Wptr + (size_t)knext * N + 64);
        }

#pragma unroll
        for (int ks = 0; ks < 2; ks++) {
            const int kk = ks * 8 + (lane & 3);
            uint32_t af[4][4], bf[4][2];
#pragma unroll
            for (int t = 0; t < 4; t++) {
                const int m = wm * 64 + t * 16 + (lane >> 2);
                af[t][0] = As[buf][kk][m];
                af[t][1] = As[buf][kk][m + 8];
                af[t][2] = As[buf][kk + 4][m];
                af[t][3] = As[buf][kk + 4][m + 8];
            }
#pragma unroll
            for (int t = 0; t < 4; t++) {
                const int n = wn * 32 + t * 8 + (lane >> 2);
                bf[t][0] = Bs[buf][kk][n];
                bf[t][1] = Bs[buf][kk + 4][n];
            }
#pragma unroll
            for (int mt = 0; mt < 4; mt++)
#pragma unroll
                for (int nt = 0; nt < 4; nt++)
                    mma_tf32(acc[mt][nt], af[mt], bf[nt]);
        }

        if (knext < K) {
            const int nb = buf ^ 1;
            As[nb][aK + 0][aM] = f2tf32(aReg0.x);
            As[nb][aK + 1][aM] = f2tf32(aReg0.y);
            As[nb][aK + 2][aM] = f2tf32(aReg0.z);
            As[nb][aK + 3][aM] = f2tf32(aReg0.w);
            As[nb][aK + 4][aM] = f2tf32(aReg1.x);
            As[nb][aK + 5][aM] = f2tf32(aReg1.y);
            As[nb][aK + 6][aM] = f2tf32(aReg1.z);
            As[nb][aK + 7][aM] = f2tf32(aReg1.w);
            uint4 p0 = {f2tf32(bReg0.x), f2tf32(bReg0.y), f2tf32(bReg0.z), f2tf32(bReg0.w)};
            uint4 p1 = {f2tf32(bReg1.x), f2tf32(bReg1.y), f2tf32(bReg1.z), f2tf32(bReg1.w)};
            *(uint4*)&Bs[nb][bK][bN]      = p0;
            *(uint4*)&Bs[nb][bK][bN + 64] = p1;
        }
        __syncthreads();
        buf ^= 1;
    }

#pragma unroll
    for (int mt = 0; mt < 4; mt++) {
        const int r = rowBase + wm * 64 + mt * 16 + (lane >> 2);
#pragma unroll
        for (int nt = 0; nt < 4; nt++) {
            const int cc = colBase + wn * 32 + nt * 8 + (lane & 3) * 2;
            const float2 bb = *(const float2*)(bias + cc);
            float2 o0, o1;
            o0.x = acc[mt][nt][0] + bb.x;
            o0.y = acc[mt][nt][1] + bb.y;
            o1.x = acc[mt][nt][2] + bb.x;
            o1.y = acc[mt][nt][3] + bb.y;
            if (RELU) {
                o0.x = fmaxf(o0.x, 0.f); o0.y = fmaxf(o0.y, 0.f);
                o1.x = fmaxf(o1.x, 0.f); o1.y = fmaxf(o1.y, 0.f);
            }
            *(float2*)(C + (size_t)r * N + cc)       = o0;
            *(float2*)(C + (size_t)(r + 8) * N + cc) = o1;
        }
    }
}

// ---------------- Tensor-core flash attention ------------------------------
// Block: 128 q-rows x one (head, batch). 8 warps, each owns a 16-row strip.
// smem:
//   Qimg : uint4 [8 warps][8 ks][32 lanes]  (A-fragment image, tf32)   32 KB
//   Ps   : uint32[64 key][136]              (P tf32, [key][qrow])      34 KB
//     (Ps doubles as Q staging [128][68] f32 before the main loop)
//   Ks   : float [64 key][76]  ([key][d])                              19 KB
//   Vs   : float [64 key][72]  ([key][d])                              18 KB
#define AQ   128
#define PST  136
#define KST  76
#define VST  72
#define QSG  68
#define OFF_PS   32768
#define OFF_KS   (OFF_PS + 64 * PST * 4)
#define OFF_VS   (OFF_KS + 64 * KST * 4)
#define ATT2_SMEM (OFF_VS + 64 * VST * 4)

__global__ __launch_bounds__(256, 2) void attention_tc_kernel(
    const float* __restrict__ Q, const float* __restrict__ K,
    const float* __restrict__ V, float* __restrict__ O)
{
    extern __shared__ char asmem[];
    uint4*    Qimg = (uint4*)asmem;
    uint32_t* Ps   = (uint32_t*)(asmem + OFF_PS);
    float*    Qstg = (float*)(asmem + OFF_PS);
    float*    Ks   = (float*)(asmem + OFF_KS);
    float*    Vs   = (float*)(asmem + OFF_VS);

    const int tid  = threadIdx.x;
    const int lane = tid & 31;
    const int warp = tid >> 5;
    const int la3  = lane & 3;
    const int lr   = lane >> 2;          // 0..7
    const int qb = blockIdx.x, h = blockIdx.y, b = blockIdx.z;

    const float* Qg = Q + ((size_t)(b * SEQLEN) + qb * AQ) * D_MODEL + h * HEAD_DIM;
    const float* Kg = K + (size_t)(b * SEQLEN) * D_MODEL + h * HEAD_DIM;
    const float* Vg = V + (size_t)(b * SEQLEN) * D_MODEL + h * HEAD_DIM;

    const uint32_t ks_base = (uint32_t)__cvta_generic_to_shared(Ks);
    const uint32_t vs_base = (uint32_t)__cvta_generic_to_shared(Vs);

    // ---- stage Q (scaled), build per-warp A-fragment image ----
#pragma unroll
    for (int i = 0; i < 8; i++) {
        int f = tid + i * 256;           // 1024 float4 = 128x64
        int r = f >> 4, d4 = (f & 15) << 2;
        float4 qv = *(const float4*)(Qg + (size_t)r * D_MODEL + d4);
        Qstg[r * QSG + d4 + 0] = qv.x * 0.125f;
        Qstg[r * QSG + d4 + 1] = qv.y * 0.125f;
        Qstg[r * QSG + d4 + 2] = qv.z * 0.125f;
        Qstg[r * QSG + d4 + 3] = qv.w * 0.125f;
    }
    __syncthreads();
    {
        const int r0 = warp * 16 + lr;
#pragma unroll
        for (int ks = 0; ks < 8; ks++) {
            uint4 af;
            af.x = f2tf32(Qstg[r0 * QSG + ks * 8 + la3]);
            af.y = f2tf32(Qstg[(r0 + 8) * QSG + ks * 8 + la3]);
            af.z = f2tf32(Qstg[r0 * QSG + ks * 8 + la3 + 4]);
            af.w = f2tf32(Qstg[(r0 + 8) * QSG + ks * 8 + la3 + 4]);
            Qimg[(warp * 8 + ks) * 32 + lane] = af;
        }
    }

    float m0 = -1e30f, m1 = -1e30f, l0 = 0.f, l1 = 0.f;
    float acc[8][4];
#pragma unroll
    for (int nt = 0; nt < 8; nt++)
#pragma unroll
        for (int r = 0; r < 4; r++) acc[nt][r] = 0.f;

    for (int kb = 0; kb < SEQLEN / 64; kb++) {
        __syncthreads();                 // everyone done with prev tiles / Qstg
        // ---- async-load K,V tiles (raw f32) ----
        const size_t tb = (size_t)(kb * 64) * D_MODEL;
#pragma unroll
        for (int i = 0; i < 4; i++) {
            int f = tid + i * 256;       // 1024 float4 = 64x64
            int r = f >> 4, d4 = (f & 15) << 2;
            cp_async16(ks_base + (r * KST + d4) * 4, Kg + tb + (size_t)r * D_MODEL + d4);
            cp_async16(vs_base + (r * VST + d4) * 4, Vg + tb + (size_t)r * D_MODEL + d4);
        }
        cp_async_commit();
        cp_async_wait0();
        __syncthreads();

        // ---- S = Q @ K^T (tf32 mma) ----
        float c[8][4];
#pragma unroll
        for (int nt = 0; nt < 8; nt++)
#pragma unroll
            for (int r = 0; r < 4; r++) c[nt][r] = 0.f;

#pragma unroll
        for (int ks = 0; ks < 8; ks++) {
            uint4 afv = Qimg[(warp * 8 + ks) * 32 + lane];
            uint32_t af[4] = {afv.x, afv.y, afv.z, afv.w};
#pragma unroll
            for (int nt = 0; nt < 8; nt++) {
                const int n = nt * 8 + lr;
                uint32_t bf[2];
                bf[0] = f2tf32(Ks[n * KST + ks * 8 + la3]);
                bf[1] = f2tf32(Ks[n * KST + ks * 8 + la3 + 4]);
                mma_tf32(c[nt], af, bf);
            }
        }

        // ---- online softmax (rows r0 = c[*][0,1], r1 = c[*][2,3]) ----
        {
            float mx0 = -1e30f, mx1 = -1e30f;
#pragma unroll
            for (int nt = 0; nt < 8; nt++) {
                mx0 = fmaxf(mx0, fmaxf(c[nt][0], c[nt][1]));
                mx1 = fmaxf(mx1, fmaxf(c[nt][2], c[nt][3]));
            }
            mx0 = fmaxf(mx0, __shfl_xor_sync(0xffffffffu, mx0, 1));
            mx0 = fmaxf(mx0, __shfl_xor_sync(0xffffffffu, mx0, 2));
            mx1 = fmaxf(mx1, __shfl_xor_sync(0xffffffffu, mx1, 1));
            mx1 = fmaxf(mx1, __shfl_xor_sync(0xffffffffu, mx1, 2));
            const float mn0 = fmaxf(m0, mx0);
            const float mn1 = fmaxf(m1, mx1);
            const float al0 = __expf(m0 - mn0);
            const float al1 = __expf(m1 - mn1);
            float s0 = 0.f, s1 = 0.f;
#pragma unroll
            for (int nt = 0; nt < 8; nt++) {
                c[nt][0] = __expf(c[nt][0] - mn0);
                c[nt][1] = __expf(c[nt][1] - mn0);
                c[nt][2] = __expf(c[nt][2] - mn1);
                c[nt][3] = __expf(c[nt][3] - mn1);
                s0 += c[nt][0] + c[nt][1];
                s1 += c[nt][2] + c[nt][3];
            }
            s0 += __shfl_xor_sync(0xffffffffu, s0, 1);
            s0 += __shfl_xor_sync(0xffffffffu, s0, 2);
            s1 += __shfl_xor_sync(0xffffffffu, s1, 1);
            s1 += __shfl_xor_sync(0xffffffffu, s1, 2);
            l0 = l0 * al0 + s0; m0 = mn0;
            l1 = l1 * al1 + s1; m1 = mn1;
#pragma unroll
            for (int nt = 0; nt < 8; nt++) {
                acc[nt][0] *= al0; acc[nt][1] *= al0;
                acc[nt][2] *= al1; acc[nt][3] *= al1;
            }
        }

        // ---- P -> smem (tf32), own rows only: warp-local ordering ----
        __syncwarp();
        {
            const int r0 = warp * 16 + lr;
#pragma unroll
            for (int nt = 0; nt < 8; nt++) {
                const int k0 = nt * 8 + la3 * 2;
                Ps[k0 * PST + r0]           = f2tf32(c[nt][0]);
                Ps[(k0 + 1) * PST + r0]     = f2tf32(c[nt][1]);
                Ps[k0 * PST + r0 + 8]       = f2tf32(c[nt][2]);
                Ps[(k0 + 1) * PST + r0 + 8] = f2tf32(c[nt][3]);
            }
        }
        __syncwarp();

        // ---- O += P @ V (tf32 mma) ----
#pragma unroll
        for (int ks = 0; ks < 8; ks++) {
            const int kk = ks * 8 + la3;
            const int r0 = warp * 16 + lr;
            uint32_t af[4];
            af[0] = Ps[kk * PST + r0];
            af[1] = Ps[kk * PST + r0 + 8];
            af[2] = Ps[(kk + 4) * PST + r0];
            af[3] = Ps[(kk + 4) * PST + r0 + 8];
#pragma unroll
            for (int nt = 0; nt < 8; nt++) {
                const int n = nt * 8 + lr;
                uint32_t bf[2];
                bf[0] = f2tf32(Vs[kk * VST + n]);
                bf[1] = f2tf32(Vs[(kk + 4) * VST + n]);
                mma_tf32(acc[nt], af, bf);
            }
        }
    }

    // ---- epilogue ----
    const float inv0 = 1.f / l0;
    const float inv1 = 1.f / l1;
    float* Og = O + ((size_t)(b * SEQLEN) + qb * AQ + warp * 16 + lr) * D_MODEL
                  + h * HEAD_DIM;
#pragma unroll
    for (int nt = 0; nt < 8; nt++) {
        const int cc = nt * 8 + la3 * 2;
        float2 o0 = {acc[nt][0] * inv0, acc[nt][1] * inv0};
        float2 o1 = {acc[nt][2] * inv1, acc[nt][3] * inv1};
        *(float2*)(Og + cc)                 = o0;
        *(float2*)(Og + 8 * D_MODEL + cc)   = o1;
    }
}

// ---------------- add + LayerNorm ------------------------------------------
__global__ __launch_bounds__(256) void add_ln_kernel(
    const float* __restrict__ A, const float* __restrict__ Hh,
    const float* __restrict__ G, const float* __restrict__ Bt,
    float* __restrict__ Out)
{
    const int row = blockIdx.x;
    const int t = threadIdx.x;
    const size_t base = (size_t)row * D_MODEL + t * 4;
    float4 x = *(const float4*)(A + base);
    float4 y = *(const float4*)(Hh + base);
    float4 v = {x.x + y.x, x.y + y.y, x.z + y.z, x.w + y.w};
    float s  = v.x + v.y + v.z + v.w;
    float s2 = v.x * v.x + v.y * v.y + v.z * v.z + v.w * v.w;
#pragma unroll
    for (int o = 16; o; o >>= 1) {
        s  += __shfl_xor_sync(0xffffffffu, s, o);
        s2 += __shfl_xor_sync(0xffffffffu, s2, o);
    }
    __shared__ float sh[16];
    __shared__ float stats[2];
    const int w = t >> 5;
    if ((t & 31) == 0) { sh[w] = s; sh[8 + w] = s2; }
    __syncthreads();
    if (t == 0) {
        float S = 0.f, S2 = 0.f;
        for (int i = 0; i < 8; i++) { S += sh[i]; S2 += sh[8 + i]; }
        float mu = S * (1.f / D_MODEL);
        float var = S2 * (1.f / D_MODEL) - mu * mu;
        stats[0] = mu;
        stats[1] = rsqrtf(var + 1e-5f);
    }
    __syncthreads();
    const float mu = stats[0], r = stats[1];
    float4 g4 = *(const float4*)(G + t * 4);
    float4 b4 = *(const float4*)(Bt + t * 4);
    float4 o;
    o.x = (v.x - mu) * r * g4.x + b4.x;
    o.y = (v.y - mu) * r * g4.y + b4.y;
    o.z = (v.z - mu) * r * g4.z + b4.z;
    o.w = (v.w - mu) * r * g4.w + b4.w;
    *(float4*)(Out + base) = o;
}

// ---------------- launch ---------------------------------------------------
static void run_gemm(const float* A, const float* W, const float* bias,
                     float* C, int M, int N, int K, bool relu)
{
    dim3 grid(N / GBN, M / GBM);
    if (relu) gemm_tf32_kernel<1><<<grid, 256>>>(A, W, bias, C, M, N, K);
    else      gemm_tf32_kernel<0><<<grid, 256>>>(A, W, bias, C, M, N, K);
}

extern "C" void kernel_launch(void* const* d_in, const int* in_sizes, int n_in,
                              void* d_out, int out_size)
{
    const float* hid   = (const float*)d_in[0];
    const float* enc   = (const float*)d_in[1];
    const float* sa_wq = (const float*)d_in[2];
    const float* sa_bq = (const float*)d_in[3];
    const float* sa_wk = (const float*)d_in[4];
    const float* sa_bk = (const float*)d_in[5];
    const float* sa_wv = (const float*)d_in[6];
    const float* sa_bv = (const float*)d_in[7];
    const float* ln1_g = (const float*)d_in[8];
    const float* ln1_b = (const float*)d_in[9];
    const float* ca_wq = (const float*)d_in[10];
    const float* ca_bq = (const float*)d_in[11];
    const float* ca_wk = (const float*)d_in[12];
    const float* ca_bk = (const float*)d_in[13];
    const float* ca_wv = (const float*)d_in[14];
    const float* ca_bv = (const float*)d_in[15];
    const float* ln2_g = (const float*)d_in[16];
    const float* ln2_b = (const float*)d_in[17];
    const float* fc1_w = (const float*)d_in[18];
    const float* fc1_b = (const float*)d_in[19];
    const float* fc2_w = (const float*)d_in[20];
    const float* fc2_b = (const float*)d_in[21];
    const float* ln3_g = (const float*)d_in[22];
    const float* ln3_b = (const float*)d_in[23];

    float *q, *k, *v, *ctx, *x1, *x2, *ffn;
    cudaGetSymbolAddress((void**)&q,   g_q);
    cudaGetSymbolAddress((void**)&k,   g_k);
    cudaGetSymbolAddress((void**)&v,   g_v);
    cudaGetSymbolAddress((void**)&ctx, g_ctx);
    cudaGetSymbolAddress((void**)&x1,  g_x1);
    cudaGetSymbolAddress((void**)&x2,  g_x2);
    cudaGetSymbolAddress((void**)&ffn, g_ffn);

    cudaFuncSetAttribute(attention_tc_kernel,
                         cudaFuncAttributeMaxDynamicSharedMemorySize, ATT2_SMEM);

    const dim3 att_grid(SEQLEN / AQ, N_HEADS, BATCH);

    // ---- self-attention ----
    run_gemm(hid, sa_wq, sa_bq, q, NTOK, D_MODEL, D_MODEL, false);
    run_gemm(hid, sa_wk, sa_bk, k, NTOK, D_MODEL, D_MODEL, false);
    run_gemm(hid, sa_wv, sa_bv, v, NTOK, D_MODEL, D_MODEL, false);
    attention_tc_kernel<<<att_grid, 256, ATT2_SMEM>>>(q, k, v, ctx);
    add_ln_kernel<<<NTOK, 256>>>(hid, ctx, ln1_g, ln1_b, x1);

    // ---- cross-attention ----
    run_gemm(x1,  ca_wq, ca_bq, q, NTOK, D_MODEL, D_MODEL, false);
    run_gemm(enc, ca_wk, ca_bk, k, NTOK, D_MODEL, D_MODEL, false);
    run_gemm(enc, ca_wv, ca_bv, v, NTOK, D_MODEL, D_MODEL, false);
    attention_tc_kernel<<<att_grid, 256, ATT2_SMEM>>>(q, k, v, ctx);
    add_ln_kernel<<<NTOK, 256>>>(x1, ctx, ln2_g, ln2_b, x2);

    // ---- feed-forward ----
    run_gemm(x2,  fc1_w, fc1_b, ffn, NTOK, FFN_DIM, D_MODEL, true);
    run_gemm(ffn, fc2_w, fc2_b, ctx, NTOK, D_MODEL, FFN_DIM, false);
    add_ln_kernel<<<NTOK, 256>>>(x2, ctx, ln3_g, ln3_b, (float*)d_out);
}

// round 8
// speedup vs baseline: 2.6570x; 1.0187x over previous
#include <cuda_runtime.h>
#include <stdint.h>

#define D_MODEL 1024
#define FFN_DIM 4096
#define N_HEADS 16
#define HEAD_DIM 64
#define SEQLEN 2048
#define BATCH 2
#define NTOK (BATCH * SEQLEN)

// ---------------- scratch (device globals: no runtime allocation) ----------
__device__ float g_q[NTOK * D_MODEL];
__device__ float g_k[NTOK * D_MODEL];
__device__ float g_v[NTOK * D_MODEL];
__device__ float g_ctx[NTOK * D_MODEL];
__device__ float g_x1[NTOK * D_MODEL];
__device__ float g_x2[NTOK * D_MODEL];
__device__ float g_ffn[(size_t)NTOK * FFN_DIM];

// ---------------- tf32 helpers ---------------------------------------------
__device__ __forceinline__ uint32_t f2tf32(float x) {
    uint32_t r;
    asm("cvt.rna.tf32.f32 %0, %1;" : "=r"(r) : "f"(x));
    return r;
}

__device__ __forceinline__ float ex2f(float x) {
    float r;
    asm("ex2.approx.ftz.f32 %0, %1;" : "=f"(r) : "f"(x));
    return r;
}

__device__ __forceinline__ void mma_tf32(
    float* c, const uint32_t* a, const uint32_t* b)
{
    asm volatile(
        "mma.sync.aligned.m16n8k8.row.col.f32.tf32.tf32.f32 "
        "{%0,%1,%2,%3}, {%4,%5,%6,%7}, {%8,%9}, {%0,%1,%2,%3};\n"
        : "+f"(c[0]), "+f"(c[1]), "+f"(c[2]), "+f"(c[3])
        : "r"(a[0]), "r"(a[1]), "r"(a[2]), "r"(a[3]),
          "r"(b[0]), "r"(b[1]));
}

__device__ __forceinline__ void cp_async16(uint32_t dst_smem, const void* src) {
    asm volatile("cp.async.ca.shared.global [%0], [%1], 16;"
                 :: "r"(dst_smem), "l"(src));
}
__device__ __forceinline__ void cp_async_commit() {
    asm volatile("cp.async.commit_group;");
}
__device__ __forceinline__ void cp_async_wait0() {
    asm volatile("cp.async.wait_group 0;" ::: "memory");
}

// ---------------- GEMM: C[M,N] = A[M,K] @ W[K,N] + bias (opt ReLU) ---------
#define GBM 128
#define GBN 128
#define GBK 16
#define GST 136

template <int RELU>
__global__ __launch_bounds__(256, 2) void gemm_tf32_kernel(
    const float* __restrict__ A, const float* __restrict__ W,
    const float* __restrict__ bias, float* __restrict__ C,
    int M, int N, int K)
{
    __shared__ uint32_t As[2][GBK][GST];
    __shared__ uint32_t Bs[2][GBK][GST];

    const int tid  = threadIdx.x;
    const int lane = tid & 31;
    const int warp = tid >> 5;
    const int wm = warp >> 2;
    const int wn = warp & 3;
    const int rowBase = blockIdx.y * GBM;
    const int colBase = blockIdx.x * GBN;

    const int aM = tid >> 1;
    const int aK = (tid & 1) * 8;
    const int bK = tid >> 4;
    const int bN = (tid & 15) * 4;

    const float* Aptr = A + (size_t)(rowBase + aM) * K + aK;
    const float* Wptr = W + (size_t)bK * N + colBase + bN;

    float acc[4][4][4];
#pragma unroll
    for (int i = 0; i < 4; i++)
#pragma unroll
        for (int j = 0; j < 4; j++)
#pragma unroll
            for (int r = 0; r < 4; r++) acc[i][j][r] = 0.f;

    float4 aReg0, aReg1, bReg0, bReg1;

    aReg0 = *(const float4*)(Aptr);
    aReg1 = *(const float4*)(Aptr + 4);
    bReg0 = *(const float4*)(Wptr);
    bReg1 = *(const float4*)(Wptr + 64);
    {
        As[0][aK + 0][aM] = f2tf32(aReg0.x);
        As[0][aK + 1][aM] = f2tf32(aReg0.y);
        As[0][aK + 2][aM] = f2tf32(aReg0.z);
        As[0][aK + 3][aM] = f2tf32(aReg0.w);
        As[0][aK + 4][aM] = f2tf32(aReg1.x);
        As[0][aK + 5][aM] = f2tf32(aReg1.y);
        As[0][aK + 6][aM] = f2tf32(aReg1.z);
        As[0][aK + 7][aM] = f2tf32(aReg1.w);
        uint4 p0 = {f2tf32(bReg0.x), f2tf32(bReg0.y), f2tf32(bReg0.z), f2tf32(bReg0.w)};
        uint4 p1 = {f2tf32(bReg1.x), f2tf32(bReg1.y), f2tf32(bReg1.z), f2tf32(bReg1.w)};
        *(uint4*)&Bs[0][bK][bN]      = p0;
        *(uint4*)&Bs[0][bK][bN + 64] = p1;
    }
    __syncthreads();

    int buf = 0;
    for (int k0 = 0; k0 < K; k0 += GBK) {
        const int knext = k0 + GBK;
        if (knext < K) {
            aReg0 = *(const float4*)(Aptr + knext);
            aReg1 = *(const float4*)(Aptr + knext + 4);
            bReg0 = *(const float4*)(Wptr + (size_t)knext * N);
            bReg1 = *(const float4*)(Wptr + (size_t)knext * N + 64);
        }

#pragma unroll
        for (int ks = 0; ks < 2; ks++) {
            const int kk = ks * 8 + (lane & 3);
            uint32_t af[4][4], bf[4][2];
#pragma unroll
            for (int t = 0; t < 4; t++) {
                const int m = wm * 64 + t * 16 + (lane >> 2);
                af[t][0] = As[buf][kk][m];
                af[t][1] = As[buf][kk][m + 8];
                af[t][2] = As[buf][kk + 4][m];
                af[t][3] = As[buf][kk + 4][m + 8];
            }
#pragma unroll
            for (int t = 0; t < 4; t++) {
                const int n = wn * 32 + t * 8 + (lane >> 2);
                bf[t][0] = Bs[buf][kk][n];
                bf[t][1] = Bs[buf][kk + 4][n];
            }
#pragma unroll
            for (int mt = 0; mt < 4; mt++)
#pragma unroll
                for (int nt = 0; nt < 4; nt++)
                    mma_tf32(acc[mt][nt], af[mt], bf[nt]);
        }

        if (knext < K) {
            const int nb = buf ^ 1;
            As[nb][aK + 0][aM] = f2tf32(aReg0.x);
            As[nb][aK + 1][aM] = f2tf32(aReg0.y);
            As[nb][aK + 2][aM] = f2tf32(aReg0.z);
            As[nb][aK + 3][aM] = f2tf32(aReg0.w);
            As[nb][aK + 4][aM] = f2tf32(aReg1.x);
            As[nb][aK + 5][aM] = f2tf32(aReg1.y);
            As[nb][aK + 6][aM] = f2tf32(aReg1.z);
            As[nb][aK + 7][aM] = f2tf32(aReg1.w);
            uint4 p0 = {f2tf32(bReg0.x), f2tf32(bReg0.y), f2tf32(bReg0.z), f2tf32(bReg0.w)};
            uint4 p1 = {f2tf32(bReg1.x), f2tf32(bReg1.y), f2tf32(bReg1.z), f2tf32(bReg1.w)};
            *(uint4*)&Bs[nb][bK][bN]      = p0;
            *(uint4*)&Bs[nb][bK][bN + 64] = p1;
        }
        __syncthreads();
        buf ^= 1;
    }

#pragma unroll
    for (int mt = 0; mt < 4; mt++) {
        const int r = rowBase + wm * 64 + mt * 16 + (lane >> 2);
#pragma unroll
        for (int nt = 0; nt < 4; nt++) {
            const int cc = colBase + wn * 32 + nt * 8 + (lane & 3) * 2;
            const float2 bb = *(const float2*)(bias + cc);
            float2 o0, o1;
            o0.x = acc[mt][nt][0] + bb.x;
            o0.y = acc[mt][nt][1] + bb.y;
            o1.x = acc[mt][nt][2] + bb.x;
            o1.y = acc[mt][nt][3] + bb.y;
            if (RELU) {
                o0.x = fmaxf(o0.x, 0.f); o0.y = fmaxf(o0.y, 0.f);
                o1.x = fmaxf(o1.x, 0.f); o1.y = fmaxf(o1.y, 0.f);
            }
            *(float2*)(C + (size_t)r * N + cc)       = o0;
            *(float2*)(C + (size_t)(r + 8) * N + cc) = o1;
        }
    }
}

// ---------------- Tensor-core flash attention ------------------------------
// Block: 128 q-rows x one (head, batch). 8 warps, each owns a 16-row strip.
// K/V tiles are cp.async'd raw, then converted ONCE into shared tf32
// B-fragment images (warp-independent), so inner loops are pure LDS.64+mma.
#define AQ   128
#define PST  136
#define KST  76
#define VST  72
#define QSG  68
#define OFF_PS   32768
#define OFF_KS   (OFF_PS + 64 * PST * 4)
#define OFF_VS   (OFF_KS + 64 * KST * 4)
#define ATT2_SMEM (OFF_VS + 64 * VST * 4)

// 0.125 * log2(e): softmax computed in base 2.
#define QSCALE 0.1803368801111204f

__global__ __launch_bounds__(256, 2) void attention_tc_kernel(
    const float* __restrict__ Q, const float* __restrict__ K,
    const float* __restrict__ V, float* __restrict__ O)
{
    extern __shared__ char asmem[];
    uint4*    Qimg = (uint4*)asmem;
    uint32_t* Ps   = (uint32_t*)(asmem + OFF_PS);
    float*    Qstg = (float*)(asmem + OFF_PS);
    float*    Ks   = (float*)(asmem + OFF_KS);
    float*    Vs   = (float*)(asmem + OFF_VS);
    uint2*    Kimg = (uint2*)(asmem + OFF_KS);   // overlays Ks (4096 <= 64*76)
    uint2*    Vimg = (uint2*)(asmem + OFF_VS);   // overlays Vs (4096 <= 64*72)

    const int tid  = threadIdx.x;
    const int lane = tid & 31;
    const int warp = tid >> 5;
    const int la3  = lane & 3;
    const int lr   = lane >> 2;          // 0..7
    const int qb = blockIdx.x, h = blockIdx.y, b = blockIdx.z;

    const float* Qg = Q + ((size_t)(b * SEQLEN) + qb * AQ) * D_MODEL + h * HEAD_DIM;
    const float* Kg = K + (size_t)(b * SEQLEN) * D_MODEL + h * HEAD_DIM;
    const float* Vg = V + (size_t)(b * SEQLEN) * D_MODEL + h * HEAD_DIM;

    const uint32_t ks_base = (uint32_t)__cvta_generic_to_shared(Ks);
    const uint32_t vs_base = (uint32_t)__cvta_generic_to_shared(Vs);

    // ---- stage Q (scaled), build per-warp A-fragment image ----
#pragma unroll
    for (int i = 0; i < 8; i++) {
        int f = tid + i * 256;           // 1024 float4 = 128x64
        int r = f >> 4, d4 = (f & 15) << 2;
        float4 qv = *(const float4*)(Qg + (size_t)r * D_MODEL + d4);
        Qstg[r * QSG + d4 + 0] = qv.x * QSCALE;
        Qstg[r * QSG + d4 + 1] = qv.y * QSCALE;
        Qstg[r * QSG + d4 + 2] = qv.z * QSCALE;
        Qstg[r * QSG + d4 + 3] = qv.w * QSCALE;
    }
    __syncthreads();
    {
        const int r0 = warp * 16 + lr;
#pragma unroll
        for (int ks = 0; ks < 8; ks++) {
            uint4 af;
            af.x = f2tf32(Qstg[r0 * QSG + ks * 8 + la3]);
            af.y = f2tf32(Qstg[(r0 + 8) * QSG + ks * 8 + la3]);
            af.z = f2tf32(Qstg[r0 * QSG + ks * 8 + la3 + 4]);
            af.w = f2tf32(Qstg[(r0 + 8) * QSG + ks * 8 + la3 + 4]);
            Qimg[(warp * 8 + ks) * 32 + lane] = af;
        }
    }

    float m0 = -1e30f, m1 = -1e30f, l0 = 0.f, l1 = 0.f;
    float acc[8][4];
#pragma unroll
    for (int nt = 0; nt < 8; nt++)
#pragma unroll
        for (int r = 0; r < 4; r++) acc[nt][r] = 0.f;

    for (int kb = 0; kb < SEQLEN / 64; kb++) {
        __syncthreads();                 // prev tile fully consumed
        // ---- async-load K,V tiles (raw f32) ----
        const size_t tb = (size_t)(kb * 64) * D_MODEL;
#pragma unroll
        for (int i = 0; i < 4; i++) {
            int f = tid + i * 256;       // 1024 float4 = 64x64
            int r = f >> 4, d4 = (f & 15) << 2;
            cp_async16(ks_base + (r * KST + d4) * 4, Kg + tb + (size_t)r * D_MODEL + d4);
            cp_async16(vs_base + (r * VST + d4) * 4, Vg + tb + (size_t)r * D_MODEL + d4);
        }
        cp_async_commit();
        cp_async_wait0();
        __syncthreads();

        // ---- convert raw tiles -> shared tf32 B-fragment images (in place) ----
        {
            float kraw[16], vraw[16];
            const int rK = warp * 8 + lr;        // K raw row this thread reads
            const int cV = warp * 8 + lr;        // V raw col this thread reads
#pragma unroll
            for (int j = 0; j < 8; j++) {
                kraw[j * 2]     = Ks[rK * KST + j * 8 + la3];
                kraw[j * 2 + 1] = Ks[rK * KST + j * 8 + la3 + 4];
                vraw[j * 2]     = Vs[(j * 8 + la3) * VST + cV];
                vraw[j * 2 + 1] = Vs[(j * 8 + la3 + 4) * VST + cV];
            }
            __syncthreads();                     // all raw reads done
#pragma unroll
            for (int j = 0; j < 8; j++) {
                uint2 kk2 = {f2tf32(kraw[j * 2]), f2tf32(kraw[j * 2 + 1])};
                uint2 vv2 = {f2tf32(vraw[j * 2]), f2tf32(vraw[j * 2 + 1])};
                Kimg[(j * 8 + warp) * 32 + lane] = kk2;   // entry (ks=j, nt=warp)
                Vimg[(j * 8 + warp) * 32 + lane] = vv2;
            }
        }
        __syncthreads();

        // ---- S = Q @ K^T (tf32 mma) ----
        float c[8][4];
#pragma unroll
        for (int nt = 0; nt < 8; nt++)
#pragma unroll
            for (int r = 0; r < 4; r++) c[nt][r] = 0.f;

#pragma unroll
        for (int ks = 0; ks < 8; ks++) {
            uint4 afv = Qimg[(warp * 8 + ks) * 32 + lane];
            uint32_t af[4] = {afv.x, afv.y, afv.z, afv.w};
#pragma unroll
            for (int nt = 0; nt < 8; nt++) {
                uint2 bf2 = Kimg[(ks * 8 + nt) * 32 + lane];
                uint32_t bf[2] = {bf2.x, bf2.y};
                mma_tf32(c[nt], af, bf);
            }
        }

        // ---- online softmax (base 2; rows r0 = c[*][0,1], r1 = c[*][2,3]) ----
        {
            float mx0 = -1e30f, mx1 = -1e30f;
#pragma unroll
            for (int nt = 0; nt < 8; nt++) {
                mx0 = fmaxf(mx0, fmaxf(c[nt][0], c[nt][1]));
                mx1 = fmaxf(mx1, fmaxf(c[nt][2], c[nt][3]));
            }
            mx0 = fmaxf(mx0, __shfl_xor_sync(0xffffffffu, mx0, 1));
            mx0 = fmaxf(mx0, __shfl_xor_sync(0xffffffffu, mx0, 2));
            mx1 = fmaxf(mx1, __shfl_xor_sync(0xffffffffu, mx1, 1));
            mx1 = fmaxf(mx1, __shfl_xor_sync(0xffffffffu, mx1, 2));
            const float mn0 = fmaxf(m0, mx0);
            const float mn1 = fmaxf(m1, mx1);
            const float al0 = ex2f(m0 - mn0);
            const float al1 = ex2f(m1 - mn1);
            float s0 = 0.f, s1 = 0.f;
#pragma unroll
            for (int nt = 0; nt < 8; nt++) {
                c[nt][0] = ex2f(c[nt][0] - mn0);
                c[nt][1] = ex2f(c[nt][1] - mn0);
                c[nt][2] = ex2f(c[nt][2] - mn1);
                c[nt][3] = ex2f(c[nt][3] - mn1);
                s0 += c[nt][0] + c[nt][1];
                s1 += c[nt][2] + c[nt][3];
            }
            s0 += __shfl_xor_sync(0xffffffffu, s0, 1);
            s0 += __shfl_xor_sync(0xffffffffu, s0, 2);
            s1 += __shfl_xor_sync(0xffffffffu, s1, 1);
            s1 += __shfl_xor_sync(0xffffffffu, s1, 2);
            l0 = l0 * al0 + s0; m0 = mn0;
            l1 = l1 * al1 + s1; m1 = mn1;
#pragma unroll
            for (int nt = 0; nt < 8; nt++) {
                acc[nt][0] *= al0; acc[nt][1] *= al0;
                acc[nt][2] *= al1; acc[nt][3] *= al1;
            }
        }

        // ---- P -> smem (tf32), own rows only: warp-local ordering ----
        __syncwarp();
        {
            const int r0 = warp * 16 + lr;
#pragma unroll
            for (int nt = 0; nt < 8; nt++) {
                const int k0 = nt * 8 + la3 * 2;
                Ps[k0 * PST + r0]           = f2tf32(c[nt][0]);
                Ps[(k0 + 1) * PST + r0]     = f2tf32(c[nt][1]);
                Ps[k0 * PST + r0 + 8]       = f2tf32(c[nt][2]);
                Ps[(k0 + 1) * PST + r0 + 8] = f2tf32(c[nt][3]);
            }
        }
        __syncwarp();

        // ---- O += P @ V (tf32 mma) ----
#pragma unroll
        for (int ks = 0; ks < 8; ks++) {
            const int kk = ks * 8 + la3;
            const int r0 = warp * 16 + lr;
            uint32_t af[4];
            af[0] = Ps[kk * PST + r0];
            af[1] = Ps[kk * PST + r0 + 8];
            af[2] = Ps[(kk + 4) * PST + r0];
            af[3] = Ps[(kk + 4) * PST + r0 + 8];
#pragma unroll
            for (int nt = 0; nt < 8; nt++) {
                uint2 bf2 = Vimg[(ks * 8 + nt) * 32 + lane];
                uint32_t bf[2] = {bf2.x, bf2.y};
                mma_tf32(acc[nt], af, bf);
            }
        }
    }

    // ---- epilogue ----
    const float inv0 = 1.f / l0;
    const float inv1 = 1.f / l1;
    float* Og = O + ((size_t)(b * SEQLEN) + qb * AQ + warp * 16 + lr) * D_MODEL
                  + h * HEAD_DIM;
#pragma unroll
    for (int nt = 0; nt < 8; nt++) {
        const int cc = nt * 8 + la3 * 2;
        float2 o0 = {acc[nt][0] * inv0, acc[nt][1] * inv0};
        float2 o1 = {acc[nt][2] * inv1, acc[nt][3] * inv1};
        *(float2*)(Og + cc)                 = o0;
        *(float2*)(Og + 8 * D_MODEL + cc)   = o1;
    }
}

// ---------------- add + LayerNorm ------------------------------------------
__global__ __launch_bounds__(256) void add_ln_kernel(
    const float* __restrict__ A, const float* __restrict__ Hh,
    const float* __restrict__ G, const float* __restrict__ Bt,
    float* __restrict__ Out)
{
    const int row = blockIdx.x;
    const int t = threadIdx.x;
    const size_t base = (size_t)row * D_MODEL + t * 4;
    float4 x = *(const float4*)(A + base);
    float4 y = *(const float4*)(Hh + base);
    float4 v = {x.x + y.x, x.y + y.y, x.z + y.z, x.w + y.w};
    float s  = v.x + v.y + v.z + v.w;
    float s2 = v.x * v.x + v.y * v.y + v.z * v.z + v.w * v.w;
#pragma unroll
    for (int o = 16; o; o >>= 1) {
        s  += __shfl_xor_sync(0xffffffffu, s, o);
        s2 += __shfl_xor_sync(0xffffffffu, s2, o);
    }
    __shared__ float sh[16];
    __shared__ float stats[2];
    const int w = t >> 5;
    if ((t & 31) == 0) { sh[w] = s; sh[8 + w] = s2; }
    __syncthreads();
    if (t == 0) {
        float S = 0.f, S2 = 0.f;
        for (int i = 0; i < 8; i++) { S += sh[i]; S2 += sh[8 + i]; }
        float mu = S * (1.f / D_MODEL);
        float var = S2 * (1.f / D_MODEL) - mu * mu;
        stats[0] = mu;
        stats[1] = rsqrtf(var + 1e-5f);
    }
    __syncthreads();
    const float mu = stats[0], r = stats[1];
    float4 g4 = *(const float4*)(G + t * 4);
    float4 b4 = *(const float4*)(Bt + t * 4);
    float4 o;
    o.x = (v.x - mu) * r * g4.x + b4.x;
    o.y = (v.y - mu) * r * g4.y + b4.y;
    o.z = (v.z - mu) * r * g4.z + b4.z;
    o.w = (v.w - mu) * r * g4.w + b4.w;
    *(float4*)(Out + base) = o;
}

// ---------------- launch ---------------------------------------------------
static void run_gemm(const float* A, const float* W, const float* bias,
                     float* C, int M, int N, int K, bool relu)
{
    dim3 grid(N / GBN, M / GBM);
    if (relu) gemm_tf32_kernel<1><<<grid, 256>>>(A, W, bias, C, M, N, K);
    else      gemm_tf32_kernel<0><<<grid, 256>>>(A, W, bias, C, M, N, K);
}

extern "C" void kernel_launch(void* const* d_in, const int* in_sizes, int n_in,
                              void* d_out, int out_size)
{
    const float* hid   = (const float*)d_in[0];
    const float* enc   = (const float*)d_in[1];
    const float* sa_wq = (const float*)d_in[2];
    const float* sa_bq = (const float*)d_in[3];
    const float* sa_wk = (const float*)d_in[4];
    const float* sa_bk = (const float*)d_in[5];
    const float* sa_wv = (const float*)d_in[6];
    const float* sa_bv = (const float*)d_in[7];
    const float* ln1_g = (const float*)d_in[8];
    const float* ln1_b = (const float*)d_in[9];
    const float* ca_wq = (const float*)d_in[10];
    const float* ca_bq = (const float*)d_in[11];
    const float* ca_wk = (const float*)d_in[12];
    const float* ca_bk = (const float*)d_in[13];
    const float* ca_wv = (const float*)d_in[14];
    const float* ca_bv = (const float*)d_in[15];
    const float* ln2_g = (const float*)d_in[16];
    const float* ln2_b = (const float*)d_in[17];
    const float* fc1_w = (const float*)d_in[18];
    const float* fc1_b = (const float*)d_in[19];
    const float* fc2_w = (const float*)d_in[20];
    const float* fc2_b = (const float*)d_in[21];
    const float* ln3_g = (const float*)d_in[22];
    const float* ln3_b = (const float*)d_in[23];

    float *q, *k, *v, *ctx, *x1, *x2, *ffn;
    cudaGetSymbolAddress((void**)&q,   g_q);
    cudaGetSymbolAddress((void**)&k,   g_k);
    cudaGetSymbolAddress((void**)&v,   g_v);
    cudaGetSymbolAddress((void**)&ctx, g_ctx);
    cudaGetSymbolAddress((void**)&x1,  g_x1);
    cudaGetSymbolAddress((void**)&x2,  g_x2);
    cudaGetSymbolAddress((void**)&ffn, g_ffn);

    cudaFuncSetAttribute(attention_tc_kernel,
                         cudaFuncAttributeMaxDynamicSharedMemorySize, ATT2_SMEM);

    const dim3 att_grid(SEQLEN / AQ, N_HEADS, BATCH);

    // ---- self-attention ----
    run_gemm(hid, sa_wq, sa_bq, q, NTOK, D_MODEL, D_MODEL, false);
    run_gemm(hid, sa_wk, sa_bk, k, NTOK, D_MODEL, D_MODEL, false);
    run_gemm(hid, sa_wv, sa_bv, v, NTOK, D_MODEL, D_MODEL, false);
    attention_tc_kernel<<<att_grid, 256, ATT2_SMEM>>>(q, k, v, ctx);
    add_ln_kernel<<<NTOK, 256>>>(hid, ctx, ln1_g, ln1_b, x1);

    // ---- cross-attention ----
    run_gemm(x1,  ca_wq, ca_bq, q, NTOK, D_MODEL, D_MODEL, false);
    run_gemm(enc, ca_wk, ca_bk, k, NTOK, D_MODEL, D_MODEL, false);
    run_gemm(enc, ca_wv, ca_bv, v, NTOK, D_MODEL, D_MODEL, false);
    attention_tc_kernel<<<att_grid, 256, ATT2_SMEM>>>(q, k, v, ctx);
    add_ln_kernel<<<NTOK, 256>>>(x1, ctx, ln2_g, ln2_b, x2);

    // ---- feed-forward ----
    run_gemm(x2,  fc1_w, fc1_b, ffn, NTOK, FFN_DIM, D_MODEL, true);
    run_gemm(ffn, fc2_w, fc2_b, ctx, NTOK, D_MODEL, FFN_DIM, false);
    add_ln_kernel<<<NTOK, 256>>>(x2, ctx, ln3_g, ln3_b, (float*)d_out);
}

// round 9
// speedup vs baseline: 2.7537x; 1.0364x over previous
#include <cuda_runtime.h>
#include <stdint.h>

#define D_MODEL 1024
#define FFN_DIM 4096
#define N_HEADS 16
#define HEAD_DIM 64
#define SEQLEN 2048
#define BATCH 2
#define NTOK (BATCH * SEQLEN)

// ---------------- scratch (device globals: no runtime allocation) ----------
__device__ float g_q[NTOK * D_MODEL];
__device__ float g_k[NTOK * D_MODEL];
__device__ float g_v[NTOK * D_MODEL];
__device__ float g_ctx[NTOK * D_MODEL];
__device__ float g_x1[NTOK * D_MODEL];
__device__ float g_x2[NTOK * D_MODEL];
__device__ float g_ffn[(size_t)NTOK * FFN_DIM];

// ---------------- tf32 helpers ---------------------------------------------
__device__ __forceinline__ uint32_t f2tf32(float x) {
    uint32_t r;
    asm("cvt.rna.tf32.f32 %0, %1;" : "=r"(r) : "f"(x));
    return r;
}

__device__ __forceinline__ float ex2f(float x) {
    float r;
    asm("ex2.approx.ftz.f32 %0, %1;" : "=f"(r) : "f"(x));
    return r;
}

__device__ __forceinline__ void mma_tf32(
    float* c, const uint32_t* a, const uint32_t* b)
{
    asm volatile(
        "mma.sync.aligned.m16n8k8.row.col.f32.tf32.tf32.f32 "
        "{%0,%1,%2,%3}, {%4,%5,%6,%7}, {%8,%9}, {%0,%1,%2,%3};\n"
        : "+f"(c[0]), "+f"(c[1]), "+f"(c[2]), "+f"(c[3])
        : "r"(a[0]), "r"(a[1]), "r"(a[2]), "r"(a[3]),
          "r"(b[0]), "r"(b[1]));
}

__device__ __forceinline__ void cp_async16(uint32_t dst_smem, const void* src) {
    asm volatile("cp.async.ca.shared.global [%0], [%1], 16;"
                 :: "r"(dst_smem), "l"(src));
}
__device__ __forceinline__ void cp_async_commit() {
    asm volatile("cp.async.commit_group;");
}
__device__ __forceinline__ void cp_async_wait0() {
    asm volatile("cp.async.wait_group 0;" ::: "memory");
}

// ---------------- GEMM: C[M,N] = A[M,K] @ W[K,N] + bias (opt ReLU) ---------
#define GBM 128
#define GBN 128
#define GBK 16
#define GST 136

template <int RELU>
__global__ __launch_bounds__(256, 2) void gemm_tf32_kernel(
    const float* __restrict__ A, const float* __restrict__ W,
    const float* __restrict__ bias, float* __restrict__ C,
    int M, int N, int K)
{
    __shared__ uint32_t As[2][GBK][GST];
    __shared__ uint32_t Bs[2][GBK][GST];

    const int tid  = threadIdx.x;
    const int lane = tid & 31;
    const int warp = tid >> 5;
    const int wm = warp >> 2;
    const int wn = warp & 3;
    const int rowBase = blockIdx.y * GBM;
    const int colBase = blockIdx.x * GBN;

    const int aM = tid >> 1;
    const int aK = (tid & 1) * 8;
    const int bK = tid >> 4;
    const int bN = (tid & 15) * 4;

    const float* Aptr = A + (size_t)(rowBase + aM) * K + aK;
    const float* Wptr = W + (size_t)bK * N + colBase + bN;

    float acc[4][4][4];
#pragma unroll
    for (int i = 0; i < 4; i++)
#pragma unroll
        for (int j = 0; j < 4; j++)
#pragma unroll
            for (int r = 0; r < 4; r++) acc[i][j][r] = 0.f;

    float4 aReg0, aReg1, bReg0, bReg1;

    aReg0 = *(const float4*)(Aptr);
    aReg1 = *(const float4*)(Aptr + 4);
    bReg0 = *(const float4*)(Wptr);
    bReg1 = *(const float4*)(Wptr + 64);
    {
        As[0][aK + 0][aM] = f2tf32(aReg0.x);
        As[0][aK + 1][aM] = f2tf32(aReg0.y);
        As[0][aK + 2][aM] = f2tf32(aReg0.z);
        As[0][aK + 3][aM] = f2tf32(aReg0.w);
        As[0][aK + 4][aM] = f2tf32(aReg1.x);
        As[0][aK + 5][aM] = f2tf32(aReg1.y);
        As[0][aK + 6][aM] = f2tf32(aReg1.z);
        As[0][aK + 7][aM] = f2tf32(aReg1.w);
        uint4 p0 = {f2tf32(bReg0.x), f2tf32(bReg0.y), f2tf32(bReg0.z), f2tf32(bReg0.w)};
        uint4 p1 = {f2tf32(bReg1.x), f2tf32(bReg1.y), f2tf32(bReg1.z), f2tf32(bReg1.w)};
        *(uint4*)&Bs[0][bK][bN]      = p0;
        *(uint4*)&Bs[0][bK][bN + 64] = p1;
    }
    __syncthreads();

    int buf = 0;
    for (int k0 = 0; k0 < K; k0 += GBK) {
        const int knext = k0 + GBK;
        if (knext < K) {
            aReg0 = *(const float4*)(Aptr + knext);
            aReg1 = *(const float4*)(Aptr + knext + 4);
            bReg0 = *(const float4*)(Wptr + (size_t)knext * N);
            bReg1 = *(const float4*)(Wptr + (size_t)knext * N + 64);
        }

#pragma unroll
        for (int ks = 0; ks < 2; ks++) {
            const int kk = ks * 8 + (lane & 3);
            uint32_t af[4][4], bf[4][2];
#pragma unroll
            for (int t = 0; t < 4; t++) {
                const int m = wm * 64 + t * 16 + (lane >> 2);
                af[t][0] = As[buf][kk][m];
                af[t][1] = As[buf][kk][m + 8];
                af[t][2] = As[buf][kk + 4][m];
                af[t][3] = As[buf][kk + 4][m + 8];
            }
#pragma unroll
            for (int t = 0; t < 4; t++) {
                const int n = wn * 32 + t * 8 + (lane >> 2);
                bf[t][0] = Bs[buf][kk][n];
                bf[t][1] = Bs[buf][kk + 4][n];
            }
#pragma unroll
            for (int mt = 0; mt < 4; mt++)
#pragma unroll
                for (int nt = 0; nt < 4; nt++)
                    mma_tf32(acc[mt][nt], af[mt], bf[nt]);
        }

        if (knext < K) {
            const int nb = buf ^ 1;
            As[nb][aK + 0][aM] = f2tf32(aReg0.x);
            As[nb][aK + 1][aM] = f2tf32(aReg0.y);
            As[nb][aK + 2][aM] = f2tf32(aReg0.z);
            As[nb][aK + 3][aM] = f2tf32(aReg0.w);
            As[nb][aK + 4][aM] = f2tf32(aReg1.x);
            As[nb][aK + 5][aM] = f2tf32(aReg1.y);
            As[nb][aK + 6][aM] = f2tf32(aReg1.z);
            As[nb][aK + 7][aM] = f2tf32(aReg1.w);
            uint4 p0 = {f2tf32(bReg0.x), f2tf32(bReg0.y), f2tf32(bReg0.z), f2tf32(bReg0.w)};
            uint4 p1 = {f2tf32(bReg1.x), f2tf32(bReg1.y), f2tf32(bReg1.z), f2tf32(bReg1.w)};
            *(uint4*)&Bs[nb][bK][bN]      = p0;
            *(uint4*)&Bs[nb][bK][bN + 64] = p1;
        }
        __syncthreads();
        buf ^= 1;
    }

#pragma unroll
    for (int mt = 0; mt < 4; mt++) {
        const int r = rowBase + wm * 64 + mt * 16 + (lane >> 2);
#pragma unroll
        for (int nt = 0; nt < 4; nt++) {
            const int cc = colBase + wn * 32 + nt * 8 + (lane & 3) * 2;
            const float2 bb = *(const float2*)(bias + cc);
            float2 o0, o1;
            o0.x = acc[mt][nt][0] + bb.x;
            o0.y = acc[mt][nt][1] + bb.y;
            o1.x = acc[mt][nt][2] + bb.x;
            o1.y = acc[mt][nt][3] + bb.y;
            if (RELU) {
                o0.x = fmaxf(o0.x, 0.f); o0.y = fmaxf(o0.y, 0.f);
                o1.x = fmaxf(o1.x, 0.f); o1.y = fmaxf(o1.y, 0.f);
            }
            *(float2*)(C + (size_t)r * N + cc)       = o0;
            *(float2*)(C + (size_t)(r + 8) * N + cc) = o1;
        }
    }
}

// ---------------- Tensor-core flash attention (256-row CTA, pipelined) -----
// 512 threads = 16 warps, each owns a 16-row strip of a 256-row q-tile.
// Raw K/V tiles land via cp.async in dedicated buffers; one convert pass
// builds shared tf32 B-fragment images; the NEXT tile's cp.async is issued
// right after convert so the DMA overlaps S/softmax/PV compute.
#define AQ2  256
#define PST2 264
#define KRST 68
#define VRST 72
#define QSG2 68
#define OFF2_PS    65536
#define OFF2_KIMG  (OFF2_PS + 64 * PST2 * 4)
#define OFF2_VIMG  (OFF2_KIMG + 16384)
#define OFF2_KRAW  (OFF2_VIMG + 16384)
#define OFF2_VRAW  (OFF2_KRAW + 64 * KRST * 4)
#define ATT3_SMEM  (OFF2_VRAW + 64 * VRST * 4)   // 201728 bytes

// 0.125 * log2(e): softmax computed in base 2.
#define QSCALE 0.1803368801111204f

__global__ __launch_bounds__(512, 1) void attention_tc_kernel(
    const float* __restrict__ Q, const float* __restrict__ K,
    const float* __restrict__ V, float* __restrict__ O)
{
    extern __shared__ char asmem[];
    uint4*    Qimg = (uint4*)asmem;                      // 16w x 8ks x 32 lanes
    uint32_t* Ps   = (uint32_t*)(asmem + OFF2_PS);       // [64 key][264]
    float*    Qstg = (float*)(asmem + OFF2_PS);          // overlay: [128][68]
    uint2*    Kimg = (uint2*)(asmem + OFF2_KIMG);        // 64 frag x 32 lanes
    uint2*    Vimg = (uint2*)(asmem + OFF2_VIMG);
    float*    Kraw = (float*)(asmem + OFF2_KRAW);        // [64][68]
    float*    Vraw = (float*)(asmem + OFF2_VRAW);        // [64][72]

    const int tid  = threadIdx.x;
    const int lane = tid & 31;
    const int warp = tid >> 5;           // 0..15
    const int la3  = lane & 3;
    const int lr   = lane >> 2;          // 0..7
    const int qb = blockIdx.x, h = blockIdx.y, b = blockIdx.z;

    const float* Qg = Q + ((size_t)(b * SEQLEN) + qb * AQ2) * D_MODEL + h * HEAD_DIM;
    const float* Kg = K + (size_t)(b * SEQLEN) * D_MODEL + h * HEAD_DIM;
    const float* Vg = V + (size_t)(b * SEQLEN) * D_MODEL + h * HEAD_DIM;

    const uint32_t kraw_base = (uint32_t)__cvta_generic_to_shared(Kraw);
    const uint32_t vraw_base = (uint32_t)__cvta_generic_to_shared(Vraw);

    // ---- prefetch tile 0 (overlaps Q staging) ----
#pragma unroll
    for (int i = 0; i < 2; i++) {
        int f = tid + i * 512, r = f >> 4, d4 = (f & 15) << 2;
        cp_async16(kraw_base + (r * KRST + d4) * 4, Kg + (size_t)r * D_MODEL + d4);
        cp_async16(vraw_base + (r * VRST + d4) * 4, Vg + (size_t)r * D_MODEL + d4);
    }
    cp_async_commit();

    // ---- stage Q (scaled) + build per-warp A-fragment image, 2 passes ----
#pragma unroll
    for (int pass = 0; pass < 2; pass++) {
        if (pass) __syncthreads();       // pass-0 readers done before overwrite
#pragma unroll
        for (int i = 0; i < 4; i++) {
            int f = tid + i * 512;       // 2048 float4 = 128x64
            int r = f >> 4, d4 = (f & 15) << 2;
            float4 qv = *(const float4*)(Qg + (size_t)(pass * 128 + r) * D_MODEL + d4);
            Qstg[r * QSG2 + d4 + 0] = qv.x * QSCALE;
            Qstg[r * QSG2 + d4 + 1] = qv.y * QSCALE;
            Qstg[r * QSG2 + d4 + 2] = qv.z * QSCALE;
            Qstg[r * QSG2 + d4 + 3] = qv.w * QSCALE;
        }
        __syncthreads();
        if ((warp >> 3) == pass) {
            const int r0 = (warp & 7) * 16 + lr;
#pragma unroll
            for (int ks = 0; ks < 8; ks++) {
                uint4 af;
                af.x = f2tf32(Qstg[r0 * QSG2 + ks * 8 + la3]);
                af.y = f2tf32(Qstg[(r0 + 8) * QSG2 + ks * 8 + la3]);
                af.z = f2tf32(Qstg[r0 * QSG2 + ks * 8 + la3 + 4]);
                af.w = f2tf32(Qstg[(r0 + 8) * QSG2 + ks * 8 + la3 + 4]);
                Qimg[(warp * 8 + ks) * 32 + lane] = af;
            }
        }
    }

    float m0 = -1e30f, m1 = -1e30f, l0 = 0.f, l1 = 0.f;
    float acc[8][4];
#pragma unroll
    for (int nt = 0; nt < 8; nt++)
#pragma unroll
        for (int r = 0; r < 4; r++) acc[nt][r] = 0.f;

    const int r0 = warp * 16 + lr;       // this thread's P/O row pair base

    for (int kb = 0; kb < SEQLEN / 64; kb++) {
        cp_async_wait0();
        __syncthreads();                 // raw ready; prev images consumed

        // ---- convert raw -> tf32 B-fragment images (4 frags per warp) ----
#pragma unroll
        for (int j = 0; j < 4; j++) {
            const int idx = warp * 4 + j;
            const int ks = idx >> 3, nt = idx & 7;
            float k0 = Kraw[(nt * 8 + lr) * KRST + ks * 8 + la3];
            float k1 = Kraw[(nt * 8 + lr) * KRST + ks * 8 + la3 + 4];
            float v0 = Vraw[(ks * 8 + la3) * VRST + nt * 8 + lr];
            float v1 = Vraw[(ks * 8 + la3 + 4) * VRST + nt * 8 + lr];
            uint2 kk2 = {f2tf32(k0), f2tf32(k1)};
            uint2 vv2 = {f2tf32(v0), f2tf32(v1)};
            Kimg[idx * 32 + lane] = kk2;
            Vimg[idx * 32 + lane] = vv2;
        }
        __syncthreads();                 // images visible; raw reads done

        // ---- issue prefetch of next tile (overlaps compute below) ----
        if (kb + 1 < SEQLEN / 64) {
            const size_t tb = (size_t)((kb + 1) * 64) * D_MODEL;
#pragma unroll
            for (int i = 0; i < 2; i++) {
                int f = tid + i * 512, r = f >> 4, d4 = (f & 15) << 2;
                cp_async16(kraw_base + (r * KRST + d4) * 4, Kg + tb + (size_t)r * D_MODEL + d4);
                cp_async16(vraw_base + (r * VRST + d4) * 4, Vg + tb + (size_t)r * D_MODEL + d4);
            }
            cp_async_commit();
        }

        // ---- S = Q @ K^T (tf32 mma) ----
        float c[8][4];
#pragma unroll
        for (int nt = 0; nt < 8; nt++)
#pragma unroll
            for (int r = 0; r < 4; r++) c[nt][r] = 0.f;

#pragma unroll
        for (int ks = 0; ks < 8; ks++) {
            uint4 afv = Qimg[(warp * 8 + ks) * 32 + lane];
            uint32_t af[4] = {afv.x, afv.y, afv.z, afv.w};
#pragma unroll
            for (int nt = 0; nt < 8; nt++) {
                uint2 bf2 = Kimg[(ks * 8 + nt) * 32 + lane];
                uint32_t bf[2] = {bf2.x, bf2.y};
                mma_tf32(c[nt], af, bf);
            }
        }

        // ---- online softmax (base 2) ----
        {
            float mx0 = -1e30f, mx1 = -1e30f;
#pragma unroll
            for (int nt = 0; nt < 8; nt++) {
                mx0 = fmaxf(mx0, fmaxf(c[nt][0], c[nt][1]));
                mx1 = fmaxf(mx1, fmaxf(c[nt][2], c[nt][3]));
            }
            mx0 = fmaxf(mx0, __shfl_xor_sync(0xffffffffu, mx0, 1));
            mx0 = fmaxf(mx0, __shfl_xor_sync(0xffffffffu, mx0, 2));
            mx1 = fmaxf(mx1, __shfl_xor_sync(0xffffffffu, mx1, 1));
            mx1 = fmaxf(mx1, __shfl_xor_sync(0xffffffffu, mx1, 2));
            const float mn0 = fmaxf(m0, mx0);
            const float mn1 = fmaxf(m1, mx1);
            const float al0 = ex2f(m0 - mn0);
            const float al1 = ex2f(m1 - mn1);
            float s0 = 0.f, s1 = 0.f;
#pragma unroll
            for (int nt = 0; nt < 8; nt++) {
                c[nt][0] = ex2f(c[nt][0] - mn0);
                c[nt][1] = ex2f(c[nt][1] - mn0);
                c[nt][2] = ex2f(c[nt][2] - mn1);
                c[nt][3] = ex2f(c[nt][3] - mn1);
                s0 += c[nt][0] + c[nt][1];
                s1 += c[nt][2] + c[nt][3];
            }
            s0 += __shfl_xor_sync(0xffffffffu, s0, 1);
            s0 += __shfl_xor_sync(0xffffffffu, s0, 2);
            s1 += __shfl_xor_sync(0xffffffffu, s1, 1);
            s1 += __shfl_xor_sync(0xffffffffu, s1, 2);
            l0 = l0 * al0 + s0; m0 = mn0;
            l1 = l1 * al1 + s1; m1 = mn1;
#pragma unroll
            for (int nt = 0; nt < 8; nt++) {
                acc[nt][0] *= al0; acc[nt][1] *= al0;
                acc[nt][2] *= al1; acc[nt][3] *= al1;
            }
        }

        // ---- P -> smem (tf32), own rows only: warp-local ordering ----
        __syncwarp();
#pragma unroll
        for (int nt = 0; nt < 8; nt++) {
            const int k0 = nt * 8 + la3 * 2;
            Ps[k0 * PST2 + r0]           = f2tf32(c[nt][0]);
            Ps[(k0 + 1) * PST2 + r0]     = f2tf32(c[nt][1]);
            Ps[k0 * PST2 + r0 + 8]       = f2tf32(c[nt][2]);
            Ps[(k0 + 1) * PST2 + r0 + 8] = f2tf32(c[nt][3]);
        }
        __syncwarp();

        // ---- O += P @ V (tf32 mma) ----
#pragma unroll
        for (int ks = 0; ks < 8; ks++) {
            const int kk = ks * 8 + la3;
            uint32_t af[4];
            af[0] = Ps[kk * PST2 + r0];
            af[1] = Ps[kk * PST2 + r0 + 8];
            af[2] = Ps[(kk + 4) * PST2 + r0];
            af[3] = Ps[(kk + 4) * PST2 + r0 + 8];
#pragma unroll
            for (int nt = 0; nt < 8; nt++) {
                uint2 bf2 = Vimg[(ks * 8 + nt) * 32 + lane];
                uint32_t bf[2] = {bf2.x, bf2.y};
                mma_tf32(acc[nt], af, bf);
            }
        }
    }

    // ---- epilogue ----
    const float inv0 = 1.f / l0;
    const float inv1 = 1.f / l1;
    float* Og = O + ((size_t)(b * SEQLEN) + qb * AQ2 + r0) * D_MODEL + h * HEAD_DIM;
#pragma unroll
    for (int nt = 0; nt < 8; nt++) {
        const int cc = nt * 8 + la3 * 2;
        float2 o0 = {acc[nt][0] * inv0, acc[nt][1] * inv0};
        float2 o1 = {acc[nt][2] * inv1, acc[nt][3] * inv1};
        *(float2*)(Og + cc)               = o0;
        *(float2*)(Og + 8 * D_MODEL + cc) = o1;
    }
}

// ---------------- add + LayerNorm ------------------------------------------
__global__ __launch_bounds__(256) void add_ln_kernel(
    const float* __restrict__ A, const float* __restrict__ Hh,
    const float* __restrict__ G, const float* __restrict__ Bt,
    float* __restrict__ Out)
{
    const int row = blockIdx.x;
    const int t = threadIdx.x;
    const size_t base = (size_t)row * D_MODEL + t * 4;
    float4 x = *(const float4*)(A + base);
    float4 y = *(const float4*)(Hh + base);
    float4 v = {x.x + y.x, x.y + y.y, x.z + y.z, x.w + y.w};
    float s  = v.x + v.y + v.z + v.w;
    float s2 = v.x * v.x + v.y * v.y + v.z * v.z + v.w * v.w;
#pragma unroll
    for (int o = 16; o; o >>= 1) {
        s  += __shfl_xor_sync(0xffffffffu, s, o);
        s2 += __shfl_xor_sync(0xffffffffu, s2, o);
    }
    __shared__ float sh[16];
    __shared__ float stats[2];
    const int w = t >> 5;
    if ((t & 31) == 0) { sh[w] = s; sh[8 + w] = s2; }
    __syncthreads();
    if (t == 0) {
        float S = 0.f, S2 = 0.f;
        for (int i = 0; i < 8; i++) { S += sh[i]; S2 += sh[8 + i]; }
        float mu = S * (1.f / D_MODEL);
        float var = S2 * (1.f / D_MODEL) - mu * mu;
        stats[0] = mu;
        stats[1] = rsqrtf(var + 1e-5f);
    }
    __syncthreads();
    const float mu = stats[0], r = stats[1];
    float4 g4 = *(const float4*)(G + t * 4);
    float4 b4 = *(const float4*)(Bt + t * 4);
    float4 o;
    o.x = (v.x - mu) * r * g4.x + b4.x;
    o.y = (v.y - mu) * r * g4.y + b4.y;
    o.z = (v.z - mu) * r * g4.z + b4.z;
    o.w = (v.w - mu) * r * g4.w + b4.w;
    *(float4*)(Out + base) = o;
}

// ---------------- launch ---------------------------------------------------
static void run_gemm(const float* A, const float* W, const float* bias,
                     float* C, int M, int N, int K, bool relu)
{
    dim3 grid(N / GBN, M / GBM);
    if (relu) gemm_tf32_kernel<1><<<grid, 256>>>(A, W, bias, C, M, N, K);
    else      gemm_tf32_kernel<0><<<grid, 256>>>(A, W, bias, C, M, N, K);
}

extern "C" void kernel_launch(void* const* d_in, const int* in_sizes, int n_in,
                              void* d_out, int out_size)
{
    const float* hid   = (const float*)d_in[0];
    const float* enc   = (const float*)d_in[1];
    const float* sa_wq = (const float*)d_in[2];
    const float* sa_bq = (const float*)d_in[3];
    const float* sa_wk = (const float*)d_in[4];
    const float* sa_bk = (const float*)d_in[5];
    const float* sa_wv = (const float*)d_in[6];
    const float* sa_bv = (const float*)d_in[7];
    const float* ln1_g = (const float*)d_in[8];
    const float* ln1_b = (const float*)d_in[9];
    const float* ca_wq = (const float*)d_in[10];
    const float* ca_bq = (const float*)d_in[11];
    const float* ca_wk = (const float*)d_in[12];
    const float* ca_bk = (const float*)d_in[13];
    const float* ca_wv = (const float*)d_in[14];
    const float* ca_bv = (const float*)d_in[15];
    const float* ln2_g = (const float*)d_in[16];
    const float* ln2_b = (const float*)d_in[17];
    const float* fc1_w = (const float*)d_in[18];
    const float* fc1_b = (const float*)d_in[19];
    const float* fc2_w = (const float*)d_in[20];
    const float* fc2_b = (const float*)d_in[21];
    const float* ln3_g = (const float*)d_in[22];
    const float* ln3_b = (const float*)d_in[23];

    float *q, *k, *v, *ctx, *x1, *x2, *ffn;
    cudaGetSymbolAddress((void**)&q,   g_q);
    cudaGetSymbolAddress((void**)&k,   g_k);
    cudaGetSymbolAddress((void**)&v,   g_v);
    cudaGetSymbolAddress((void**)&ctx, g_ctx);
    cudaGetSymbolAddress((void**)&x1,  g_x1);
    cudaGetSymbolAddress((void**)&x2,  g_x2);
    cudaGetSymbolAddress((void**)&ffn, g_ffn);

    cudaFuncSetAttribute(attention_tc_kernel,
                         cudaFuncAttributeMaxDynamicSharedMemorySize, ATT3_SMEM);

    const dim3 att_grid(SEQLEN / AQ2, N_HEADS, BATCH);

    // ---- self-attention ----
    run_gemm(hid, sa_wq, sa_bq, q, NTOK, D_MODEL, D_MODEL, false);
    run_gemm(hid, sa_wk, sa_bk, k, NTOK, D_MODEL, D_MODEL, false);
    run_gemm(hid, sa_wv, sa_bv, v, NTOK, D_MODEL, D_MODEL, false);
    attention_tc_kernel<<<att_grid, 512, ATT3_SMEM>>>(q, k, v, ctx);
    add_ln_kernel<<<NTOK, 256>>>(hid, ctx, ln1_g, ln1_b, x1);

    // ---- cross-attention ----
    run_gemm(x1,  ca_wq, ca_bq, q, NTOK, D_MODEL, D_MODEL, false);
    run_gemm(enc, ca_wk, ca_bk, k, NTOK, D_MODEL, D_MODEL, false);
    run_gemm(enc, ca_wv, ca_bv, v, NTOK, D_MODEL, D_MODEL, false);
    attention_tc_kernel<<<att_grid, 512, ATT3_SMEM>>>(q, k, v, ctx);
    add_ln_kernel<<<NTOK, 256>>>(x1, ctx, ln2_g, ln2_b, x2);

    // ---- feed-forward ----
    run_gemm(x2,  fc1_w, fc1_b, ffn, NTOK, FFN_DIM, D_MODEL, true);
    run_gemm(ffn, fc2_w, fc2_b, ctx, NTOK, D_MODEL, FFN_DIM, false);
    add_ln_kernel<<<NTOK, 256>>>(x2, ctx, ln3_g, ln3_b, (float*)d_out);
}

// round 10
// speedup vs baseline: 2.8109x; 1.0208x over previous
#include <cuda_runtime.h>
#include <stdint.h>

#define D_MODEL 1024
#define FFN_DIM 4096
#define N_HEADS 16
#define HEAD_DIM 64
#define SEQLEN 2048
#define BATCH 2
#define NTOK (BATCH * SEQLEN)

// ---------------- scratch (device globals: no runtime allocation) ----------
__device__ float g_q[NTOK * D_MODEL];
__device__ float g_k[NTOK * D_MODEL];
__device__ float g_v[NTOK * D_MODEL];
__device__ float g_ctx[NTOK * D_MODEL];
__device__ float g_x1[NTOK * D_MODEL];
__device__ float g_x2[NTOK * D_MODEL];
__device__ float g_ffn[(size_t)NTOK * FFN_DIM];

// ---------------- tf32 helpers ---------------------------------------------
__device__ __forceinline__ uint32_t f2tf32(float x) {
    uint32_t r;
    asm("cvt.rna.tf32.f32 %0, %1;" : "=r"(r) : "f"(x));
    return r;
}

__device__ __forceinline__ float ex2f(float x) {
    float r;
    asm("ex2.approx.ftz.f32 %0, %1;" : "=f"(r) : "f"(x));
    return r;
}

__device__ __forceinline__ void mma_tf32(
    float* c, const uint32_t* a, const uint32_t* b)
{
    asm volatile(
        "mma.sync.aligned.m16n8k8.row.col.f32.tf32.tf32.f32 "
        "{%0,%1,%2,%3}, {%4,%5,%6,%7}, {%8,%9}, {%0,%1,%2,%3};\n"
        : "+f"(c[0]), "+f"(c[1]), "+f"(c[2]), "+f"(c[3])
        : "r"(a[0]), "r"(a[1]), "r"(a[2]), "r"(a[3]),
          "r"(b[0]), "r"(b[1]));
}

__device__ __forceinline__ void cp_async16(uint32_t dst_smem, const void* src) {
    asm volatile("cp.async.ca.shared.global [%0], [%1], 16;"
                 :: "r"(dst_smem), "l"(src));
}
__device__ __forceinline__ void cp_async_commit() {
    asm volatile("cp.async.commit_group;");
}
__device__ __forceinline__ void cp_async_wait0() {
    asm volatile("cp.async.wait_group 0;" ::: "memory");
}

// ---------------- GEMM: C[M,N] = A[M,K] @ W[K,N] + bias (opt ReLU) ---------
#define GBM 128
#define GBN 128
#define GBK 16
#define GST 136

template <int RELU>
__global__ __launch_bounds__(256, 2) void gemm_tf32_kernel(
    const float* __restrict__ A, const float* __restrict__ W,
    const float* __restrict__ bias, float* __restrict__ C,
    int M, int N, int K)
{
    __shared__ uint32_t As[2][GBK][GST];
    __shared__ uint32_t Bs[2][GBK][GST];

    const int tid  = threadIdx.x;
    const int lane = tid & 31;
    const int warp = tid >> 5;
    const int wm = warp >> 2;
    const int wn = warp & 3;
    const int rowBase = blockIdx.y * GBM;
    const int colBase = blockIdx.x * GBN;

    const int aM = tid >> 1;
    const int aK = (tid & 1) * 8;
    const int bK = tid >> 4;
    const int bN = (tid & 15) * 4;

    const float* Aptr = A + (size_t)(rowBase + aM) * K + aK;
    const float* Wptr = W + (size_t)bK * N + colBase + bN;

    float acc[4][4][4];
#pragma unroll
    for (int i = 0; i < 4; i++)
#pragma unroll
        for (int j = 0; j < 4; j++)
#pragma unroll
            for (int r = 0; r < 4; r++) acc[i][j][r] = 0.f;

    float4 aReg0, aReg1, bReg0, bReg1;

    aReg0 = *(const float4*)(Aptr);
    aReg1 = *(const float4*)(Aptr + 4);
    bReg0 = *(const float4*)(Wptr);
    bReg1 = *(const float4*)(Wptr + 64);
    {
        As[0][aK + 0][aM] = f2tf32(aReg0.x);
        As[0][aK + 1][aM] = f2tf32(aReg0.y);
        As[0][aK + 2][aM] = f2tf32(aReg0.z);
        As[0][aK + 3][aM] = f2tf32(aReg0.w);
        As[0][aK + 4][aM] = f2tf32(aReg1.x);
        As[0][aK + 5][aM] = f2tf32(aReg1.y);
        As[0][aK + 6][aM] = f2tf32(aReg1.z);
        As[0][aK + 7][aM] = f2tf32(aReg1.w);
        uint4 p0 = {f2tf32(bReg0.x), f2tf32(bReg0.y), f2tf32(bReg0.z), f2tf32(bReg0.w)};
        uint4 p1 = {f2tf32(bReg1.x), f2tf32(bReg1.y), f2tf32(bReg1.z), f2tf32(bReg1.w)};
        *(uint4*)&Bs[0][bK][bN]      = p0;
        *(uint4*)&Bs[0][bK][bN + 64] = p1;
    }
    __syncthreads();

    int buf = 0;
    for (int k0 = 0; k0 < K; k0 += GBK) {
        const int knext = k0 + GBK;
        if (knext < K) {
            aReg0 = *(const float4*)(Aptr + knext);
            aReg1 = *(const float4*)(Aptr + knext + 4);
            bReg0 = *(const float4*)(Wptr + (size_t)knext * N);
            bReg1 = *(const float4*)(Wptr + (size_t)knext * N + 64);
        }

#pragma unroll
        for (int ks = 0; ks < 2; ks++) {
            const int kk = ks * 8 + (lane & 3);
            uint32_t af[4][4], bf[4][2];
#pragma unroll
            for (int t = 0; t < 4; t++) {
                const int m = wm * 64 + t * 16 + (lane >> 2);
                af[t][0] = As[buf][kk][m];
                af[t][1] = As[buf][kk][m + 8];
                af[t][2] = As[buf][kk + 4][m];
                af[t][3] = As[buf][kk + 4][m + 8];
            }
#pragma unroll
            for (int t = 0; t < 4; t++) {
                const int n = wn * 32 + t * 8 + (lane >> 2);
                bf[t][0] = Bs[buf][kk][n];
                bf[t][1] = Bs[buf][kk + 4][n];
            }
#pragma unroll
            for (int mt = 0; mt < 4; mt++)
#pragma unroll
                for (int nt = 0; nt < 4; nt++)
                    mma_tf32(acc[mt][nt], af[mt], bf[nt]);
        }

        if (knext < K) {
            const int nb = buf ^ 1;
            As[nb][aK + 0][aM] = f2tf32(aReg0.x);
            As[nb][aK + 1][aM] = f2tf32(aReg0.y);
            As[nb][aK + 2][aM] = f2tf32(aReg0.z);
            As[nb][aK + 3][aM] = f2tf32(aReg0.w);
            As[nb][aK + 4][aM] = f2tf32(aReg1.x);
            As[nb][aK + 5][aM] = f2tf32(aReg1.y);
            As[nb][aK + 6][aM] = f2tf32(aReg1.z);
            As[nb][aK + 7][aM] = f2tf32(aReg1.w);
            uint4 p0 = {f2tf32(bReg0.x), f2tf32(bReg0.y), f2tf32(bReg0.z), f2tf32(bReg0.w)};
            uint4 p1 = {f2tf32(bReg1.x), f2tf32(bReg1.y), f2tf32(bReg1.z), f2tf32(bReg1.w)};
            *(uint4*)&Bs[nb][bK][bN]      = p0;
            *(uint4*)&Bs[nb][bK][bN + 64] = p1;
        }
        __syncthreads();
        buf ^= 1;
    }

#pragma unroll
    for (int mt = 0; mt < 4; mt++) {
        const int r = rowBase + wm * 64 + mt * 16 + (lane >> 2);
#pragma unroll
        for (int nt = 0; nt < 4; nt++) {
            const int cc = colBase + wn * 32 + nt * 8 + (lane & 3) * 2;
            const float2 bb = *(const float2*)(bias + cc);
            float2 o0, o1;
            o0.x = acc[mt][nt][0] + bb.x;
            o0.y = acc[mt][nt][1] + bb.y;
            o1.x = acc[mt][nt][2] + bb.x;
            o1.y = acc[mt][nt][3] + bb.y;
            if (RELU) {
                o0.x = fmaxf(o0.x, 0.f); o0.y = fmaxf(o0.y, 0.f);
                o1.x = fmaxf(o1.x, 0.f); o1.y = fmaxf(o1.y, 0.f);
            }
            *(float2*)(C + (size_t)r * N + cc)       = o0;
            *(float2*)(C + (size_t)(r + 8) * N + cc) = o1;
        }
    }
}

// ---------------- Tensor-core flash attention ------------------------------
// 256 threads = 8 warps, each owns a 32-row strip (2 m-tiles) of a 256-row
// q-tile. Each K/V B-fragment is loaded ONCE per warp and feeds TWO mmas,
// halving the dominant redundant smem traffic. cp.async prefetch of tile
// kb+1 overlaps compute on tile kb.
#define AQ2  256
#define PST2 268     // mod 32 == 12: P stores AND loads conflict-free
#define KRST 68
#define VRST 72
#define QSG2 68
#define OFF2_PS    65536
#define OFF2_KIMG  (OFF2_PS + 64 * PST2 * 4)
#define OFF2_VIMG  (OFF2_KIMG + 16384)
#define OFF2_KRAW  (OFF2_VIMG + 16384)
#define OFF2_VRAW  (OFF2_KRAW + 64 * KRST * 4)
#define ATT3_SMEM  (OFF2_VRAW + 64 * VRST * 4)   // 202752 bytes

// 0.125 * log2(e): softmax computed in base 2.
#define QSCALE 0.1803368801111204f

__global__ __launch_bounds__(256, 1) void attention_tc_kernel(
    const float* __restrict__ Q, const float* __restrict__ K,
    const float* __restrict__ V, float* __restrict__ O)
{
    extern __shared__ char asmem[];
    uint4*    Qimg = (uint4*)asmem;                      // 8w x 2mt x 8ks x 32
    uint32_t* Ps   = (uint32_t*)(asmem + OFF2_PS);       // [64 key][268]
    float*    Qstg = (float*)(asmem + OFF2_PS);          // overlay: [128][68]
    uint2*    Kimg = (uint2*)(asmem + OFF2_KIMG);        // 64 frag x 32 lanes
    uint2*    Vimg = (uint2*)(asmem + OFF2_VIMG);
    float*    Kraw = (float*)(asmem + OFF2_KRAW);        // [64][68]
    float*    Vraw = (float*)(asmem + OFF2_VRAW);        // [64][72]

    const int tid  = threadIdx.x;
    const int lane = tid & 31;
    const int warp = tid >> 5;           // 0..7
    const int la3  = lane & 3;
    const int lr   = lane >> 2;          // 0..7
    const int qb = blockIdx.x, h = blockIdx.y, b = blockIdx.z;

    const float* Qg = Q + ((size_t)(b * SEQLEN) + qb * AQ2) * D_MODEL + h * HEAD_DIM;
    const float* Kg = K + (size_t)(b * SEQLEN) * D_MODEL + h * HEAD_DIM;
    const float* Vg = V + (size_t)(b * SEQLEN) * D_MODEL + h * HEAD_DIM;

    const uint32_t kraw_base = (uint32_t)__cvta_generic_to_shared(Kraw);
    const uint32_t vraw_base = (uint32_t)__cvta_generic_to_shared(Vraw);

    // ---- prefetch tile 0 (overlaps Q staging) ----
#pragma unroll
    for (int i = 0; i < 4; i++) {
        int f = tid + i * 256, r = f >> 4, d4 = (f & 15) << 2;
        cp_async16(kraw_base + (r * KRST + d4) * 4, Kg + (size_t)r * D_MODEL + d4);
        cp_async16(vraw_base + (r * VRST + d4) * 4, Vg + (size_t)r * D_MODEL + d4);
    }
    cp_async_commit();

    // ---- stage Q (scaled) + build per-warp A-fragment images, 2 passes ----
    // pass p stages rows [p*128, p*128+128); warps p*4..p*4+3 build fragments.
#pragma unroll
    for (int pass = 0; pass < 2; pass++) {
        if (pass) __syncthreads();       // pass-0 readers done before overwrite
#pragma unroll
        for (int i = 0; i < 8; i++) {
            int f = tid + i * 256;       // 2048 float4 = 128x64
            int r = f >> 4, d4 = (f & 15) << 2;
            float4 qv = *(const float4*)(Qg + (size_t)(pass * 128 + r) * D_MODEL + d4);
            Qstg[r * QSG2 + d4 + 0] = qv.x * QSCALE;
            Qstg[r * QSG2 + d4 + 1] = qv.y * QSCALE;
            Qstg[r * QSG2 + d4 + 2] = qv.z * QSCALE;
            Qstg[r * QSG2 + d4 + 3] = qv.w * QSCALE;
        }
        __syncthreads();
        if ((warp >> 2) == pass) {
            const int rloc = (warp & 3) * 32 + lr;   // local row in staged 128
#pragma unroll
            for (int mt = 0; mt < 2; mt++) {
                const int rm = rloc + mt * 16;
#pragma unroll
                for (int ks = 0; ks < 8; ks++) {
                    uint4 af;
                    af.x = f2tf32(Qstg[rm * QSG2 + ks * 8 + la3]);
                    af.y = f2tf32(Qstg[(rm + 8) * QSG2 + ks * 8 + la3]);
                    af.z = f2tf32(Qstg[rm * QSG2 + ks * 8 + la3 + 4]);
                    af.w = f2tf32(Qstg[(rm + 8) * QSG2 + ks * 8 + la3 + 4]);
                    Qimg[((warp * 2 + mt) * 8 + ks) * 32 + lane] = af;
                }
            }
        }
    }

    float mrow[4], lrow[4];
#pragma unroll
    for (int g = 0; g < 4; g++) { mrow[g] = -1e30f; lrow[g] = 0.f; }
    float acc[2][8][4];
#pragma unroll
    for (int mt = 0; mt < 2; mt++)
#pragma unroll
        for (int nt = 0; nt < 8; nt++)
#pragma unroll
            for (int r = 0; r < 4; r++) acc[mt][nt][r] = 0.f;

    const int r0 = warp * 32 + lr;       // m-tile 0 row base; m-tile 1 = +16

    for (int kb = 0; kb < SEQLEN / 64; kb++) {
        cp_async_wait0();
        __syncthreads();                 // raw ready; prev images consumed

        // ---- convert raw -> tf32 B-fragment images (8 frags per warp) ----
#pragma unroll
        for (int j = 0; j < 8; j++) {
            const int idx = warp * 8 + j;
            const int ks = idx >> 3, nt = idx & 7;
            float k0 = Kraw[(nt * 8 + lr) * KRST + ks * 8 + la3];
            float k1 = Kraw[(nt * 8 + lr) * KRST + ks * 8 + la3 + 4];
            float v0 = Vraw[(ks * 8 + la3) * VRST + nt * 8 + lr];
            float v1 = Vraw[(ks * 8 + la3 + 4) * VRST + nt * 8 + lr];
            uint2 kk2 = {f2tf32(k0), f2tf32(k1)};
            uint2 vv2 = {f2tf32(v0), f2tf32(v1)};
            Kimg[idx * 32 + lane] = kk2;
            Vimg[idx * 32 + lane] = vv2;
        }
        __syncthreads();                 // images visible; raw reads done

        // ---- issue prefetch of next tile (overlaps compute below) ----
        if (kb + 1 < SEQLEN / 64) {
            const size_t tb = (size_t)((kb + 1) * 64) * D_MODEL;
#pragma unroll
            for (int i = 0; i < 4; i++) {
                int f = tid + i * 256, r = f >> 4, d4 = (f & 15) << 2;
                cp_async16(kraw_base + (r * KRST + d4) * 4, Kg + tb + (size_t)r * D_MODEL + d4);
                cp_async16(vraw_base + (r * VRST + d4) * 4, Vg + tb + (size_t)r * D_MODEL + d4);
            }
            cp_async_commit();
        }

        // ---- S = Q @ K^T : each B-fragment feeds both m-tiles ----
        float c[2][8][4];
#pragma unroll
        for (int mt = 0; mt < 2; mt++)
#pragma unroll
            for (int nt = 0; nt < 8; nt++)
#pragma unroll
                for (int r = 0; r < 4; r++) c[mt][nt][r] = 0.f;

#pragma unroll
        for (int ks = 0; ks < 8; ks++) {
            uint4 a0v = Qimg[((warp * 2 + 0) * 8 + ks) * 32 + lane];
            uint4 a1v = Qimg[((warp * 2 + 1) * 8 + ks) * 32 + lane];
            uint32_t a0[4] = {a0v.x, a0v.y, a0v.z, a0v.w};
            uint32_t a1[4] = {a1v.x, a1v.y, a1v.z, a1v.w};
#pragma unroll
            for (int nt = 0; nt < 8; nt++) {
                uint2 bf2 = Kimg[(ks * 8 + nt) * 32 + lane];
                uint32_t bf[2] = {bf2.x, bf2.y};
                mma_tf32(c[0][nt], a0, bf);
                mma_tf32(c[1][nt], a1, bf);
            }
        }

        // ---- online softmax (base 2); 4 row-groups per thread ----
#pragma unroll
        for (int mt = 0; mt < 2; mt++) {
            float mx0 = -1e30f, mx1 = -1e30f;
#pragma unroll
            for (int nt = 0; nt < 8; nt++) {
                mx0 = fmaxf(mx0, fmaxf(c[mt][nt][0], c[mt][nt][1]));
                mx1 = fmaxf(mx1, fmaxf(c[mt][nt][2], c[mt][nt][3]));
            }
            mx0 = fmaxf(mx0, __shfl_xor_sync(0xffffffffu, mx0, 1));
            mx0 = fmaxf(mx0, __shfl_xor_sync(0xffffffffu, mx0, 2));
            mx1 = fmaxf(mx1, __shfl_xor_sync(0xffffffffu, mx1, 1));
            mx1 = fmaxf(mx1, __shfl_xor_sync(0xffffffffu, mx1, 2));
            const int g0 = mt * 2, g1 = mt * 2 + 1;
            const float mn0 = fmaxf(mrow[g0], mx0);
            const float mn1 = fmaxf(mrow[g1], mx1);
            const float al0 = ex2f(mrow[g0] - mn0);
            const float al1 = ex2f(mrow[g1] - mn1);
            float s0 = 0.f, s1 = 0.f;
#pragma unroll
            for (int nt = 0; nt < 8; nt++) {
                c[mt][nt][0] = ex2f(c[mt][nt][0] - mn0);
                c[mt][nt][1] = ex2f(c[mt][nt][1] - mn0);
                c[mt][nt][2] = ex2f(c[mt][nt][2] - mn1);
                c[mt][nt][3] = ex2f(c[mt][nt][3] - mn1);
                s0 += c[mt][nt][0] + c[mt][nt][1];
                s1 += c[mt][nt][2] + c[mt][nt][3];
            }
            s0 += __shfl_xor_sync(0xffffffffu, s0, 1);
            s0 += __shfl_xor_sync(0xffffffffu, s0, 2);
            s1 += __shfl_xor_sync(0xffffffffu, s1, 1);
            s1 += __shfl_xor_sync(0xffffffffu, s1, 2);
            lrow[g0] = lrow[g0] * al0 + s0; mrow[g0] = mn0;
            lrow[g1] = lrow[g1] * al1 + s1; mrow[g1] = mn1;
#pragma unroll
            for (int nt = 0; nt < 8; nt++) {
                acc[mt][nt][0] *= al0; acc[mt][nt][1] *= al0;
                acc[mt][nt][2] *= al1; acc[mt][nt][3] *= al1;
            }
        }

        // ---- P -> smem (tf32), own rows only: warp-local ordering ----
        __syncwarp();
#pragma unroll
        for (int mt = 0; mt < 2; mt++) {
            const int rm = r0 + mt * 16;
#pragma unroll
            for (int nt = 0; nt < 8; nt++) {
                const int k0 = nt * 8 + la3 * 2;
                Ps[k0 * PST2 + rm]           = f2tf32(c[mt][nt][0]);
                Ps[(k0 + 1) * PST2 + rm]     = f2tf32(c[mt][nt][1]);
                Ps[k0 * PST2 + rm + 8]       = f2tf32(c[mt][nt][2]);
                Ps[(k0 + 1) * PST2 + rm + 8] = f2tf32(c[mt][nt][3]);
            }
        }
        __syncwarp();

        // ---- O += P @ V : each B-fragment feeds both m-tiles ----
#pragma unroll
        for (int ks = 0; ks < 8; ks++) {
            const int kk = ks * 8 + la3;
            uint32_t a0[4], a1[4];
            a0[0] = Ps[kk * PST2 + r0];
            a0[1] = Ps[kk * PST2 + r0 + 8];
            a0[2] = Ps[(kk + 4) * PST2 + r0];
            a0[3] = Ps[(kk + 4) * PST2 + r0 + 8];
            a1[0] = Ps[kk * PST2 + r0 + 16];
            a1[1] = Ps[kk * PST2 + r0 + 24];
            a1[2] = Ps[(kk + 4) * PST2 + r0 + 16];
            a1[3] = Ps[(kk + 4) * PST2 + r0 + 24];
#pragma unroll
            for (int nt = 0; nt < 8; nt++) {
                uint2 bf2 = Vimg[(ks * 8 + nt) * 32 + lane];
                uint32_t bf[2] = {bf2.x, bf2.y};
                mma_tf32(acc[0][nt], a0, bf);
                mma_tf32(acc[1][nt], a1, bf);
            }
        }
    }

    // ---- epilogue ----
#pragma unroll
    for (int mt = 0; mt < 2; mt++) {
        const float inv0 = 1.f / lrow[mt * 2];
        const float inv1 = 1.f / lrow[mt * 2 + 1];
        float* Og = O + ((size_t)(b * SEQLEN) + qb * AQ2 + r0 + mt * 16) * D_MODEL
                      + h * HEAD_DIM;
#pragma unroll
        for (int nt = 0; nt < 8; nt++) {
            const int cc = nt * 8 + la3 * 2;
            float2 o0 = {acc[mt][nt][0] * inv0, acc[mt][nt][1] * inv0};
            float2 o1 = {acc[mt][nt][2] * inv1, acc[mt][nt][3] * inv1};
            *(float2*)(Og + cc)               = o0;
            *(float2*)(Og + 8 * D_MODEL + cc) = o1;
        }
    }
}

// ---------------- add + LayerNorm ------------------------------------------
__global__ __launch_bounds__(256) void add_ln_kernel(
    const float* __restrict__ A, const float* __restrict__ Hh,
    const float* __restrict__ G, const float* __restrict__ Bt,
    float* __restrict__ Out)
{
    const int row = blockIdx.x;
    const int t = threadIdx.x;
    const size_t base = (size_t)row * D_MODEL + t * 4;
    float4 x = *(const float4*)(A + base);
    float4 y = *(const float4*)(Hh + base);
    float4 v = {x.x + y.x, x.y + y.y, x.z + y.z, x.w + y.w};
    float s  = v.x + v.y + v.z + v.w;
    float s2 = v.x * v.x + v.y * v.y + v.z * v.z + v.w * v.w;
#pragma unroll
    for (int o = 16; o; o >>= 1) {
        s  += __shfl_xor_sync(0xffffffffu, s, o);
        s2 += __shfl_xor_sync(0xffffffffu, s2, o);
    }
    __shared__ float sh[16];
    __shared__ float stats[2];
    const int w = t >> 5;
    if ((t & 31) == 0) { sh[w] = s; sh[8 + w] = s2; }
    __syncthreads();
    if (t == 0) {
        float S = 0.f, S2 = 0.f;
        for (int i = 0; i < 8; i++) { S += sh[i]; S2 += sh[8 + i]; }
        float mu = S * (1.f / D_MODEL);
        float var = S2 * (1.f / D_MODEL) - mu * mu;
        stats[0] = mu;
        stats[1] = rsqrtf(var + 1e-5f);
    }
    __syncthreads();
    const float mu = stats[0], r = stats[1];
    float4 g4 = *(const float4*)(G + t * 4);
    float4 b4 = *(const float4*)(Bt + t * 4);
    float4 o;
    o.x = (v.x - mu) * r * g4.x + b4.x;
    o.y = (v.y - mu) * r * g4.y + b4.y;
    o.z = (v.z - mu) * r * g4.z + b4.z;
    o.w = (v.w - mu) * r * g4.w + b4.w;
    *(float4*)(Out + base) = o;
}

// ---------------- launch ---------------------------------------------------
static void run_gemm(const float* A, const float* W, const float* bias,
                     float* C, int M, int N, int K, bool relu)
{
    dim3 grid(N / GBN, M / GBM);
    if (relu) gemm_tf32_kernel<1><<<grid, 256>>>(A, W, bias, C, M, N, K);
    else      gemm_tf32_kernel<0><<<grid, 256>>>(A, W, bias, C, M, N, K);
}

extern "C" void kernel_launch(void* const* d_in, const int* in_sizes, int n_in,
                              void* d_out, int out_size)
{
    const float* hid   = (const float*)d_in[0];
    const float* enc   = (const float*)d_in[1];
    const float* sa_wq = (const float*)d_in[2];
    const float* sa_bq = (const float*)d_in[3];
    const float* sa_wk = (const float*)d_in[4];
    const float* sa_bk = (const float*)d_in[5];
    const float* sa_wv = (const float*)d_in[6];
    const float* sa_bv = (const float*)d_in[7];
    const float* ln1_g = (const float*)d_in[8];
    const float* ln1_b = (const float*)d_in[9];
    const float* ca_wq = (const float*)d_in[10];
    const float* ca_bq = (const float*)d_in[11];
    const float* ca_wk = (const float*)d_in[12];
    const float* ca_bk = (const float*)d_in[13];
    const float* ca_wv = (const float*)d_in[14];
    const float* ca_bv = (const float*)d_in[15];
    const float* ln2_g = (const float*)d_in[16];
    const float* ln2_b = (const float*)d_in[17];
    const float* fc1_w = (const float*)d_in[18];
    const float* fc1_b = (const float*)d_in[19];
    const float* fc2_w = (const float*)d_in[20];
    const float* fc2_b = (const float*)d_in[21];
    const float* ln3_g = (const float*)d_in[22];
    const float* ln3_b = (const float*)d_in[23];

    float *q, *k, *v, *ctx, *x1, *x2, *ffn;
    cudaGetSymbolAddress((void**)&q,   g_q);
    cudaGetSymbolAddress((void**)&k,   g_k);
    cudaGetSymbolAddress((void**)&v,   g_v);
    cudaGetSymbolAddress((void**)&ctx, g_ctx);
    cudaGetSymbolAddress((void**)&x1,  g_x1);
    cudaGetSymbolAddress((void**)&x2,  g_x2);
    cudaGetSymbolAddress((void**)&ffn, g_ffn);

    cudaFuncSetAttribute(attention_tc_kernel,
                         cudaFuncAttributeMaxDynamicSharedMemorySize, ATT3_SMEM);

    const dim3 att_grid(SEQLEN / AQ2, N_HEADS, BATCH);

    // ---- self-attention ----
    run_gemm(hid, sa_wq, sa_bq, q, NTOK, D_MODEL, D_MODEL, false);
    run_gemm(hid, sa_wk, sa_bk, k, NTOK, D_MODEL, D_MODEL, false);
    run_gemm(hid, sa_wv, sa_bv, v, NTOK, D_MODEL, D_MODEL, false);
    attention_tc_kernel<<<att_grid, 256, ATT3_SMEM>>>(q, k, v, ctx);
    add_ln_kernel<<<NTOK, 256>>>(hid, ctx, ln1_g, ln1_b, x1);

    // ---- cross-attention ----
    run_gemm(x1,  ca_wq, ca_bq, q, NTOK, D_MODEL, D_MODEL, false);
    run_gemm(enc, ca_wk, ca_bk, k, NTOK, D_MODEL, D_MODEL, false);
    run_gemm(enc, ca_wv, ca_bv, v, NTOK, D_MODEL, D_MODEL, false);
    attention_tc_kernel<<<att_grid, 256, ATT3_SMEM>>>(q, k, v, ctx);
    add_ln_kernel<<<NTOK, 256>>>(x1, ctx, ln2_g, ln2_b, x2);

    // ---- feed-forward ----
    run_gemm(x2,  fc1_w, fc1_b, ffn, NTOK, FFN_DIM, D_MODEL, true);
    run_gemm(ffn, fc2_w, fc2_b, ctx, NTOK, D_MODEL, FFN_DIM, false);
    add_ln_kernel<<<NTOK, 256>>>(x2, ctx, ln3_g, ln3_b, (float*)d_out);
}

// round 12
// speedup vs baseline: 3.0343x; 1.0795x over previous
#include <cuda_runtime.h>
#include <stdint.h>

#define D_MODEL 1024
#define FFN_DIM 4096
#define N_HEADS 16
#define HEAD_DIM 64
#define SEQLEN 2048
#define BATCH 2
#define NTOK (BATCH * SEQLEN)

// ---------------- scratch (device globals: no runtime allocation) ----------
__device__ float g_q[NTOK * D_MODEL];
__device__ float g_k[NTOK * D_MODEL];
__device__ float g_v[NTOK * D_MODEL];
__device__ float g_ctx[NTOK * D_MODEL];
__device__ float g_x1[NTOK * D_MODEL];
__device__ float g_x2[NTOK * D_MODEL];
__device__ float g_ffn[(size_t)NTOK * FFN_DIM];

// ---------------- tf32 helpers ---------------------------------------------
__device__ __forceinline__ uint32_t f2tf32(float x) {
    uint32_t r;
    asm("cvt.rna.tf32.f32 %0, %1;" : "=r"(r) : "f"(x));
    return r;
}

__device__ __forceinline__ float ex2f(float x) {
    float r;
    asm("ex2.approx.ftz.f32 %0, %1;" : "=f"(r) : "f"(x));
    return r;
}

__device__ __forceinline__ void mma_tf32(
    float* c, const uint32_t* a, const uint32_t* b)
{
    asm volatile(
        "mma.sync.aligned.m16n8k8.row.col.f32.tf32.tf32.f32 "
        "{%0,%1,%2,%3}, {%4,%5,%6,%7}, {%8,%9}, {%0,%1,%2,%3};\n"
        : "+f"(c[0]), "+f"(c[1]), "+f"(c[2]), "+f"(c[3])
        : "r"(a[0]), "r"(a[1]), "r"(a[2]), "r"(a[3]),
          "r"(b[0]), "r"(b[1]));
}

__device__ __forceinline__ void cp_async16(uint32_t dst_smem, const void* src) {
    asm volatile("cp.async.ca.shared.global [%0], [%1], 16;"
                 :: "r"(dst_smem), "l"(src));
}
__device__ __forceinline__ void cp_async_commit() {
    asm volatile("cp.async.commit_group;");
}
__device__ __forceinline__ void cp_async_wait0() {
    asm volatile("cp.async.wait_group 0;" ::: "memory");
}
__device__ __forceinline__ void cp_async_wait2() {
    asm volatile("cp.async.wait_group 2;" ::: "memory");
}

// ---------------- GEMM: 4-stage cp.async pipeline, up to 3 weight mats -----
// C[M,Nper] = A[M,K] @ W[K,Nper] + bias (opt ReLU), per matrix.
// Block tile 128x128, BK=16, 256 threads, warp tile 64x32.
// smem raw f32: A [4][128][20] ([m][k], stride 20 -> conflict-free frags),
//               B [4][16][136] ([k][n], stride 136 -> conflict-free frags).
// tf32 conversion happens at fragment load (cvt.rna).
#define GA_ST 20
#define GB_ST 136
#define GEMM_SMEM ((4 * 128 * GA_ST + 4 * 16 * GB_ST) * 4)   // 75776 B

template <int RELU>
__global__ __launch_bounds__(256, 2) void gemm_cp_kernel(
    const float* __restrict__ A,
    const float* __restrict__ W0, const float* __restrict__ bias0, float* __restrict__ C0,
    const float* __restrict__ W1, const float* __restrict__ bias1, float* __restrict__ C1,
    const float* __restrict__ W2, const float* __restrict__ bias2, float* __restrict__ C2,
    int M, int N, int K, int bpm)
{
    extern __shared__ float gsm[];
    float* Asm = gsm;                    // [4][128][GA_ST]
    float* Bsm = gsm + 4 * 128 * GA_ST;  // [4][16][GB_ST]

    const int tid  = threadIdx.x;
    const int lane = tid & 31;
    const int warp = tid >> 5;
    const int wm = warp >> 2, wn = warp & 3;
    const int la3 = lane & 3, lr = lane >> 2;
    const int mat = blockIdx.x / bpm;
    const int colBase = (blockIdx.x % bpm) * 128;
    const int rowBase = blockIdx.y * 128;

    const float* W    = (mat == 0) ? W0    : (mat == 1) ? W1    : W2;
    const float* bias = (mat == 0) ? bias0 : (mat == 1) ? bias1 : bias2;
    float*       C    = (mat == 0) ? C0    : (mat == 1) ? C1    : C2;

    const uint32_t a_base = (uint32_t)__cvta_generic_to_shared(Asm);
    const uint32_t b_base = (uint32_t)__cvta_generic_to_shared(Bsm);

    // per-thread cp.async coordinates
    const int aRow = tid >> 2;             // 0..63 (+64 for second chunk)
    const int aKc  = (tid & 3) * 4;        // 0,4,8,12
    const int bK   = tid >> 5;             // 0..7  (+8 for second chunk)
    const int bN   = (tid & 31) * 4;       // 0..124

    const float* Abase = A + (size_t)(rowBase + aRow) * K + aKc;
    const float* Wbase = W + (size_t)bK * N + colBase + bN;

    float acc[4][4][4];
#pragma unroll
    for (int i = 0; i < 4; i++)
#pragma unroll
        for (int j = 0; j < 4; j++)
#pragma unroll
            for (int r = 0; r < 4; r++) acc[i][j][r] = 0.f;

    const int nstages = K / 16;

    // stage issuer: raw f32 tiles
    auto issue_stage = [&](int s) {
        if (s < nstages) {
            const int k0 = s * 16;
            const int st = s & 3;
            const float* Ap = Abase + k0;
            cp_async16(a_base + (uint32_t)(((st * 128 + aRow) * GA_ST + aKc) * 4), Ap);
            cp_async16(a_base + (uint32_t)(((st * 128 + aRow + 64) * GA_ST + aKc) * 4),
                       Ap + (size_t)64 * K);
            const float* Wp = Wbase + (size_t)k0 * N;
            cp_async16(b_base + (uint32_t)(((st * 16 + bK) * GB_ST + bN) * 4), Wp);
            cp_async16(b_base + (uint32_t)(((st * 16 + bK + 8) * GB_ST + bN) * 4),
                       Wp + (size_t)8 * N);
        }
        cp_async_commit();
    };

    issue_stage(0);
    issue_stage(1);
    issue_stage(2);

    for (int s = 0; s < nstages; s++) {
        cp_async_wait2();                // stage s resident
        __syncthreads();                 // all threads' copies visible; all
                                         // warps done computing stage s-1
        issue_stage(s + 3);              // fills buffer (s-1)&3 — safe now

        const int st = s & 3;
        const float* Ast = Asm + st * 128 * GA_ST;
        const float* Bst = Bsm + st * 16 * GB_ST;

#pragma unroll
        for (int ks = 0; ks < 2; ks++) {
            const int kc = ks * 8 + la3;
            uint32_t af[4][4], bf[4][2];
#pragma unroll
            for (int mt = 0; mt < 4; mt++) {
                const int m = wm * 64 + mt * 16 + lr;
                af[mt][0] = f2tf32(Ast[m * GA_ST + kc]);
                af[mt][1] = f2tf32(Ast[(m + 8) * GA_ST + kc]);
                af[mt][2] = f2tf32(Ast[m * GA_ST + kc + 4]);
                af[mt][3] = f2tf32(Ast[(m + 8) * GA_ST + kc + 4]);
            }
#pragma unroll
            for (int nt = 0; nt < 4; nt++) {
                const int n = wn * 32 + nt * 8 + lr;
                bf[nt][0] = f2tf32(Bst[kc * GB_ST + n]);
                bf[nt][1] = f2tf32(Bst[(kc + 4) * GB_ST + n]);
            }
#pragma unroll
            for (int mt = 0; mt < 4; mt++)
#pragma unroll
                for (int nt = 0; nt < 4; nt++)
                    mma_tf32(acc[mt][nt], af[mt], bf[nt]);
        }
    }

    // ---- epilogue: bias (+ReLU), float2 stores ----
#pragma unroll
    for (int mt = 0; mt < 4; mt++) {
        const int r = rowBase + wm * 64 + mt * 16 + lr;
#pragma unroll
        for (int nt = 0; nt < 4; nt++) {
            const int cc = colBase + wn * 32 + nt * 8 + la3 * 2;
            const float2 bb = *(const float2*)(bias + cc);
            float2 o0, o1;
            o0.x = acc[mt][nt][0] + bb.x;
            o0.y = acc[mt][nt][1] + bb.y;
            o1.x = acc[mt][nt][2] + bb.x;
            o1.y = acc[mt][nt][3] + bb.y;
            if (RELU) {
                o0.x = fmaxf(o0.x, 0.f); o0.y = fmaxf(o0.y, 0.f);
                o1.x = fmaxf(o1.x, 0.f); o1.y = fmaxf(o1.y, 0.f);
            }
            *(float2*)(C + (size_t)r * N + cc)       = o0;
            *(float2*)(C + (size_t)(r + 8) * N + cc) = o1;
        }
    }
}

// ---------------- Tensor-core flash attention (unchanged from R10) ---------
#define AQ2  256
#define PST2 268
#define KRST 68
#define VRST 72
#define QSG2 68
#define OFF2_PS    65536
#define OFF2_KIMG  (OFF2_PS + 64 * PST2 * 4)
#define OFF2_VIMG  (OFF2_KIMG + 16384)
#define OFF2_KRAW  (OFF2_VIMG + 16384)
#define OFF2_VRAW  (OFF2_KRAW + 64 * KRST * 4)
#define ATT3_SMEM  (OFF2_VRAW + 64 * VRST * 4)

#define QSCALE 0.1803368801111204f

__global__ __launch_bounds__(256, 1) void attention_tc_kernel(
    const float* __restrict__ Q, const float* __restrict__ K,
    const float* __restrict__ V, float* __restrict__ O)
{
    extern __shared__ char asmem[];
    uint4*    Qimg = (uint4*)asmem;
    uint32_t* Ps   = (uint32_t*)(asmem + OFF2_PS);
    float*    Qstg = (float*)(asmem + OFF2_PS);
    uint2*    Kimg = (uint2*)(asmem + OFF2_KIMG);
    uint2*    Vimg = (uint2*)(asmem + OFF2_VIMG);
    float*    Kraw = (float*)(asmem + OFF2_KRAW);
    float*    Vraw = (float*)(asmem + OFF2_VRAW);

    const int tid  = threadIdx.x;
    const int lane = tid & 31;
    const int warp = tid >> 5;
    const int la3  = lane & 3;
    const int lr   = lane >> 2;
    const int qb = blockIdx.x, h = blockIdx.y, b = blockIdx.z;

    const float* Qg = Q + ((size_t)(b * SEQLEN) + qb * AQ2) * D_MODEL + h * HEAD_DIM;
    const float* Kg = K + (size_t)(b * SEQLEN) * D_MODEL + h * HEAD_DIM;
    const float* Vg = V + (size_t)(b * SEQLEN) * D_MODEL + h * HEAD_DIM;

    const uint32_t kraw_base = (uint32_t)__cvta_generic_to_shared(Kraw);
    const uint32_t vraw_base = (uint32_t)__cvta_generic_to_shared(Vraw);

#pragma unroll
    for (int i = 0; i < 4; i++) {
        int f = tid + i * 256, r = f >> 4, d4 = (f & 15) << 2;
        cp_async16(kraw_base + (r * KRST + d4) * 4, Kg + (size_t)r * D_MODEL + d4);
        cp_async16(vraw_base + (r * VRST + d4) * 4, Vg + (size_t)r * D_MODEL + d4);
    }
    cp_async_commit();

#pragma unroll
    for (int pass = 0; pass < 2; pass++) {
        if (pass) __syncthreads();
#pragma unroll
        for (int i = 0; i < 8; i++) {
            int f = tid + i * 256;
            int r = f >> 4, d4 = (f & 15) << 2;
            float4 qv = *(const float4*)(Qg + (size_t)(pass * 128 + r) * D_MODEL + d4);
            Qstg[r * QSG2 + d4 + 0] = qv.x * QSCALE;
            Qstg[r * QSG2 + d4 + 1] = qv.y * QSCALE;
            Qstg[r * QSG2 + d4 + 2] = qv.z * QSCALE;
            Qstg[r * QSG2 + d4 + 3] = qv.w * QSCALE;
        }
        __syncthreads();
        if ((warp >> 2) == pass) {
            const int rloc = (warp & 3) * 32 + lr;
#pragma unroll
            for (int mt = 0; mt < 2; mt++) {
                const int rm = rloc + mt * 16;
#pragma unroll
                for (int ks = 0; ks < 8; ks++) {
                    uint4 af;
                    af.x = f2tf32(Qstg[rm * QSG2 + ks * 8 + la3]);
                    af.y = f2tf32(Qstg[(rm + 8) * QSG2 + ks * 8 + la3]);
                    af.z = f2tf32(Qstg[rm * QSG2 + ks * 8 + la3 + 4]);
                    af.w = f2tf32(Qstg[(rm + 8) * QSG2 + ks * 8 + la3 + 4]);
                    Qimg[((warp * 2 + mt) * 8 + ks) * 32 + lane] = af;
                }
            }
        }
    }

    float mrow[4], lrow[4];
#pragma unroll
    for (int g = 0; g < 4; g++) { mrow[g] = -1e30f; lrow[g] = 0.f; }
    float acc[2][8][4];
#pragma unroll
    for (int mt = 0; mt < 2; mt++)
#pragma unroll
        for (int nt = 0; nt < 8; nt++)
#pragma unroll
            for (int r = 0; r < 4; r++) acc[mt][nt][r] = 0.f;

    const int r0 = warp * 32 + lr;

    for (int kb = 0; kb < SEQLEN / 64; kb++) {
        cp_async_wait0();
        __syncthreads();

#pragma unroll
        for (int j = 0; j < 8; j++) {
            const int idx = warp * 8 + j;
            const int ks = idx >> 3, nt = idx & 7;
            float k0 = Kraw[(nt * 8 + lr) * KRST + ks * 8 + la3];
            float k1 = Kraw[(nt * 8 + lr) * KRST + ks * 8 + la3 + 4];
            float v0 = Vraw[(ks * 8 + la3) * VRST + nt * 8 + lr];
            float v1 = Vraw[(ks * 8 + la3 + 4) * VRST + nt * 8 + lr];
            uint2 kk2 = {f2tf32(k0), f2tf32(k1)};
            uint2 vv2 = {f2tf32(v0), f2tf32(v1)};
            Kimg[idx * 32 + lane] = kk2;
            Vimg[idx * 32 + lane] = vv2;
        }
        __syncthreads();

        if (kb + 1 < SEQLEN / 64) {
            const size_t tb = (size_t)((kb + 1) * 64) * D_MODEL;
#pragma unroll
            for (int i = 0; i < 4; i++) {
                int f = tid + i * 256, r = f >> 4, d4 = (f & 15) << 2;
                cp_async16(kraw_base + (r * KRST + d4) * 4, Kg + tb + (size_t)r * D_MODEL + d4);
                cp_async16(vraw_base + (r * VRST + d4) * 4, Vg + tb + (size_t)r * D_MODEL + d4);
            }
            cp_async_commit();
        }

        float c[2][8][4];
#pragma unroll
        for (int mt = 0; mt < 2; mt++)
#pragma unroll
            for (int nt = 0; nt < 8; nt++)
#pragma unroll
                for (int r = 0; r < 4; r++) c[mt][nt][r] = 0.f;

#pragma unroll
        for (int ks = 0; ks < 8; ks++) {
            uint4 a0v = Qimg[((warp * 2 + 0) * 8 + ks) * 32 + lane];
            uint4 a1v = Qimg[((warp * 2 + 1) * 8 + ks) * 32 + lane];
            uint32_t a0[4] = {a0v.x, a0v.y, a0v.z, a0v.w};
            uint32_t a1[4] = {a1v.x, a1v.y, a1v.z, a1v.w};
#pragma unroll
            for (int nt = 0; nt < 8; nt++) {
                uint2 bf2 = Kimg[(ks * 8 + nt) * 32 + lane];
                uint32_t bf[2] = {bf2.x, bf2.y};
                mma_tf32(c[0][nt], a0, bf);
                mma_tf32(c[1][nt], a1, bf);
            }
        }

#pragma unroll
        for (int mt = 0; mt < 2; mt++) {
            float mx0 = -1e30f, mx1 = -1e30f;
#pragma unroll
            for (int nt = 0; nt < 8; nt++) {
                mx0 = fmaxf(mx0, fmaxf(c[mt][nt][0], c[mt][nt][1]));
                mx1 = fmaxf(mx1, fmaxf(c[mt][nt][2], c[mt][nt][3]));
            }
            mx0 = fmaxf(mx0, __shfl_xor_sync(0xffffffffu, mx0, 1));
            mx0 = fmaxf(mx0, __shfl_xor_sync(0xffffffffu, mx0, 2));
            mx1 = fmaxf(mx1, __shfl_xor_sync(0xffffffffu, mx1, 1));
            mx1 = fmaxf(mx1, __shfl_xor_sync(0xffffffffu, mx1, 2));
            const int g0 = mt * 2, g1 = mt * 2 + 1;
            const float mn0 = fmaxf(mrow[g0], mx0);
            const float mn1 = fmaxf(mrow[g1], mx1);
            const float al0 = ex2f(mrow[g0] - mn0);
            const float al1 = ex2f(mrow[g1] - mn1);
            float s0 = 0.f, s1 = 0.f;
#pragma unroll
            for (int nt = 0; nt < 8; nt++) {
                c[mt][nt][0] = ex2f(c[mt][nt][0] - mn0);
                c[mt][nt][1] = ex2f(c[mt][nt][1] - mn0);
                c[mt][nt][2] = ex2f(c[mt][nt][2] - mn1);
                c[mt][nt][3] = ex2f(c[mt][nt][3] - mn1);
                s0 += c[mt][nt][0] + c[mt][nt][1];
                s1 += c[mt][nt][2] + c[mt][nt][3];
            }
            s0 += __shfl_xor_sync(0xffffffffu, s0, 1);
            s0 += __shfl_xor_sync(0xffffffffu, s0, 2);
            s1 += __shfl_xor_sync(0xffffffffu, s1, 1);
            s1 += __shfl_xor_sync(0xffffffffu, s1, 2);
            lrow[g0] = lrow[g0] * al0 + s0; mrow[g0] = mn0;
            lrow[g1] = lrow[g1] * al1 + s1; mrow[g1] = mn1;
#pragma unroll
            for (int nt = 0; nt < 8; nt++) {
                acc[mt][nt][0] *= al0; acc[mt][nt][1] *= al0;
                acc[mt][nt][2] *= al1; acc[mt][nt][3] *= al1;
            }
        }

        __syncwarp();
#pragma unroll
        for (int mt = 0; mt < 2; mt++) {
            const int rm = r0 + mt * 16;
#pragma unroll
            for (int nt = 0; nt < 8; nt++) {
                const int k0 = nt * 8 + la3 * 2;
                Ps[k0 * PST2 + rm]           = f2tf32(c[mt][nt][0]);
                Ps[(k0 + 1) * PST2 + rm]     = f2tf32(c[mt][nt][1]);
                Ps[k0 * PST2 + rm + 8]       = f2tf32(c[mt][nt][2]);
                Ps[(k0 + 1) * PST2 + rm + 8] = f2tf32(c[mt][nt][3]);
            }
        }
        __syncwarp();

#pragma unroll
        for (int ks = 0; ks < 8; ks++) {
            const int kk = ks * 8 + la3;
            uint32_t a0[4], a1[4];
            a0[0] = Ps[kk * PST2 + r0];
            a0[1] = Ps[kk * PST2 + r0 + 8];
            a0[2] = Ps[(kk + 4) * PST2 + r0];
            a0[3] = Ps[(kk + 4) * PST2 + r0 + 8];
            a1[0] = Ps[kk * PST2 + r0 + 16];
            a1[1] = Ps[kk * PST2 + r0 + 24];
            a1[2] = Ps[(kk + 4) * PST2 + r0 + 16];
            a1[3] = Ps[(kk + 4) * PST2 + r0 + 24];
#pragma unroll
            for (int nt = 0; nt < 8; nt++) {
                uint2 bf2 = Vimg[(ks * 8 + nt) * 32 + lane];
                uint32_t bf[2] = {bf2.x, bf2.y};
                mma_tf32(acc[0][nt], a0, bf);
                mma_tf32(acc[1][nt], a1, bf);
            }
        }
    }

#pragma unroll
    for (int mt = 0; mt < 2; mt++) {
        const float inv0 = 1.f / lrow[mt * 2];
        const float inv1 = 1.f / lrow[mt * 2 + 1];
        float* Og = O + ((size_t)(b * SEQLEN) + qb * AQ2 + r0 + mt * 16) * D_MODEL
                      + h * HEAD_DIM;
#pragma unroll
        for (int nt = 0; nt < 8; nt++) {
            const int cc = nt * 8 + la3 * 2;
            float2 o0 = {acc[mt][nt][0] * inv0, acc[mt][nt][1] * inv0};
            float2 o1 = {acc[mt][nt][2] * inv1, acc[mt][nt][3] * inv1};
            *(float2*)(Og + cc)               = o0;
            *(float2*)(Og + 8 * D_MODEL + cc) = o1;
        }
    }
}

// ---------------- add + LayerNorm ------------------------------------------
__global__ __launch_bounds__(256) void add_ln_kernel(
    const float* __restrict__ A, const float* __restrict__ Hh,
    const float* __restrict__ G, const float* __restrict__ Bt,
    float* __restrict__ Out)
{
    const int row = blockIdx.x;
    const int t = threadIdx.x;
    const size_t base = (size_t)row * D_MODEL + t * 4;
    float4 x = *(const float4*)(A + base);
    float4 y = *(const float4*)(Hh + base);
    float4 v = {x.x + y.x, x.y + y.y, x.z + y.z, x.w + y.w};
    float s  = v.x + v.y + v.z + v.w;
    float s2 = v.x * v.x + v.y * v.y + v.z * v.z + v.w * v.w;
#pragma unroll
    for (int o = 16; o; o >>= 1) {
        s  += __shfl_xor_sync(0xffffffffu, s, o);
        s2 += __shfl_xor_sync(0xffffffffu, s2, o);
    }
    __shared__ float sh[16];
    __shared__ float stats[2];
    const int w = t >> 5;
    if ((t & 31) == 0) { sh[w] = s; sh[8 + w] = s2; }
    __syncthreads();
    if (t == 0) {
        float S = 0.f, S2 = 0.f;
        for (int i = 0; i < 8; i++) { S += sh[i]; S2 += sh[8 + i]; }
        float mu = S * (1.f / D_MODEL);
        float var = S2 * (1.f / D_MODEL) - mu * mu;
        stats[0] = mu;
        stats[1] = rsqrtf(var + 1e-5f);
    }
    __syncthreads();
    const float mu = stats[0], r = stats[1];
    float4 g4 = *(const float4*)(G + t * 4);
    float4 b4 = *(const float4*)(Bt + t * 4);
    float4 o;
    o.x = (v.x - mu) * r * g4.x + b4.x;
    o.y = (v.y - mu) * r * g4.y + b4.y;
    o.z = (v.z - mu) * r * g4.z + b4.z;
    o.w = (v.w - mu) * r * g4.w + b4.w;
    *(float4*)(Out + base) = o;
}

// ---------------- launch ---------------------------------------------------
extern "C" void kernel_launch(void* const* d_in, const int* in_sizes, int n_in,
                              void* d_out, int out_size)
{
    const float* hid   = (const float*)d_in[0];
    const float* enc   = (const float*)d_in[1];
    const float* sa_wq = (const float*)d_in[2];
    const float* sa_bq = (const float*)d_in[3];
    const float* sa_wk = (const float*)d_in[4];
    const float* sa_bk = (const float*)d_in[5];
    const float* sa_wv = (const float*)d_in[6];
    const float* sa_bv = (const float*)d_in[7];
    const float* ln1_g = (const float*)d_in[8];
    const float* ln1_b = (const float*)d_in[9];
    const float* ca_wq = (const float*)d_in[10];
    const float* ca_bq = (const float*)d_in[11];
    const float* ca_wk = (const float*)d_in[12];
    const float* ca_bk = (const float*)d_in[13];
    const float* ca_wv = (const float*)d_in[14];
    const float* ca_bv = (const float*)d_in[15];
    const float* ln2_g = (const float*)d_in[16];
    const float* ln2_b = (const float*)d_in[17];
    const float* fc1_w = (const float*)d_in[18];
    const float* fc1_b = (const float*)d_in[19];
    const float* fc2_w = (const float*)d_in[20];
    const float* fc2_b = (const float*)d_in[21];
    const float* ln3_g = (const float*)d_in[22];
    const float* ln3_b = (const float*)d_in[23];

    float *q, *k, *v, *ctx, *x1, *x2, *ffn;
    cudaGetSymbolAddress((void**)&q,   g_q);
    cudaGetSymbolAddress((void**)&k,   g_k);
    cudaGetSymbolAddress((void**)&v,   g_v);
    cudaGetSymbolAddress((void**)&ctx, g_ctx);
    cudaGetSymbolAddress((void**)&x1,  g_x1);
    cudaGetSymbolAddress((void**)&x2,  g_x2);
    cudaGetSymbolAddress((void**)&ffn, g_ffn);

    cudaFuncSetAttribute(attention_tc_kernel,
                         cudaFuncAttributeMaxDynamicSharedMemorySize, ATT3_SMEM);
    cudaFuncSetAttribute(gemm_cp_kernel<0>,
                         cudaFuncAttributeMaxDynamicSharedMemorySize, GEMM_SMEM);
    cudaFuncSetAttribute(gemm_cp_kernel<1>,
                         cudaFuncAttributeMaxDynamicSharedMemorySize, GEMM_SMEM);

    const dim3 att_grid(SEQLEN / AQ2, N_HEADS, BATCH);

    // ---- self-attention: fused QKV projection (one launch) ----
    gemm_cp_kernel<0><<<dim3(24, 32), 256, GEMM_SMEM>>>(
        hid, sa_wq, sa_bq, q, sa_wk, sa_bk, k, sa_wv, sa_bv, v,
        NTOK, D_MODEL, D_MODEL, 8);
    attention_tc_kernel<<<att_grid, 256, ATT3_SMEM>>>(q, k, v, ctx);
    add_ln_kernel<<<NTOK, 256>>>(hid, ctx, ln1_g, ln1_b, x1);

    // ---- cross-attention: Q from x1; fused K,V from enc ----
    gemm_cp_kernel<0><<<dim3(8, 32), 256, GEMM_SMEM>>>(
        x1, ca_wq, ca_bq, q, ca_wq, ca_bq, q, ca_wq, ca_bq, q,
        NTOK, D_MODEL, D_MODEL, 8);
    gemm_cp_kernel<0><<<dim3(16, 32), 256, GEMM_SMEM>>>(
        enc, ca_wk, ca_bk, k, ca_wv, ca_bv, v, ca_wv, ca_bv, v,
        NTOK, D_MODEL, D_MODEL, 8);
    attention_tc_kernel<<<att_grid, 256, ATT3_SMEM>>>(q, k, v, ctx);
    add_ln_kernel<<<NTOK, 256>>>(x1, ctx, ln2_g, ln2_b, x2);

    // ---- feed-forward ----
    gemm_cp_kernel<1><<<dim3(32, 32), 256, GEMM_SMEM>>>(
        x2, fc1_w, fc1_b, ffn, fc1_w, fc1_b, ffn, fc1_w, fc1_b, ffn,
        NTOK, FFN_DIM, D_MODEL, 32);
    gemm_cp_kernel<0><<<dim3(8, 32), 256, GEMM_SMEM>>>(
        ffn, fc2_w, fc2_b, ctx, fc2_w, fc2_b, ctx, fc2_w, fc2_b, ctx,
        NTOK, D_MODEL, FFN_DIM, 8);
    add_ln_kernel<<<NTOK, 256>>>(x2, ctx, ln3_g, ln3_b, (float*)d_out);
}